// round 6
// baseline (speedup 1.0000x reference)
#include <cuda_runtime.h>
#include <cuda_bf16.h>
#include <cstdint>
#include <math.h>

// Problem constants
#define BB 2
#define TT 2048
#define EMB 1024
#define HEADS 16
#define HS 64
#define NROWS (BB*TT)          // 4096
#define GK 1024                // K for both GEMMs

// ---------------------------------------------------------------------------
// Scratch (__device__ globals; allocation-free rule)
// ---------------------------------------------------------------------------
__device__ __nv_bfloat16 g_qhi[(size_t)BB*HEADS*TT*HS];  // [bh][t][d], pre-scaled 0.125
__device__ __nv_bfloat16 g_qlo[(size_t)BB*HEADS*TT*HS];
__device__ __nv_bfloat16 g_khi[(size_t)BB*HEADS*TT*HS];
__device__ __nv_bfloat16 g_klo[(size_t)BB*HEADS*TT*HS];
__device__ __nv_bfloat16 g_vhi[(size_t)BB*HEADS*TT*HS];
__device__ __nv_bfloat16 g_vlo[(size_t)BB*HEADS*TT*HS];

__device__ __nv_bfloat16 g_xhi[(size_t)NROWS*GK];
__device__ __nv_bfloat16 g_xlo[(size_t)NROWS*GK];
__device__ __nv_bfloat16 g_ahi[(size_t)NROWS*GK];        // attention out (proj input)
__device__ __nv_bfloat16 g_alo[(size_t)NROWS*GK];
__device__ __nv_bfloat16 g_wqhi[(size_t)3*EMB*GK];       // [3072][1024] K-major
__device__ __nv_bfloat16 g_wqlo[(size_t)3*EMB*GK];
__device__ __nv_bfloat16 g_wphi[(size_t)EMB*GK];         // [1024][1024] K-major
__device__ __nv_bfloat16 g_wplo[(size_t)EMB*GK];

// ---------------------------------------------------------------------------
// PTX helpers (portable sm_80+ subset: ldmatrix / mma.sync / cp.async)
// ---------------------------------------------------------------------------
__device__ __forceinline__ uint32_t smem_u32(const void* p) {
    uint32_t a;
    asm("{ .reg .u64 t; cvta.to.shared.u64 t, %1; cvt.u32.u64 %0, t; }" : "=r"(a) : "l"(p));
    return a;
}
__device__ __forceinline__ void cp16(uint32_t dst, const void* src) {
    asm volatile("cp.async.cg.shared.global [%0], [%1], 16;" :: "r"(dst), "l"(src));
}
__device__ __forceinline__ void cp_commit() {
    asm volatile("cp.async.commit_group;" ::: "memory");
}
template<int N>
__device__ __forceinline__ void cp_wait() {
    asm volatile("cp.async.wait_group %0;" :: "n"(N) : "memory");
}
__device__ __forceinline__ void ldsm4(uint32_t* r, uint32_t a) {
    asm volatile("ldmatrix.sync.aligned.m8n8.x4.shared.b16 {%0,%1,%2,%3}, [%4];"
        : "=r"(r[0]), "=r"(r[1]), "=r"(r[2]), "=r"(r[3]) : "r"(a));
}
// non-trans x2: for [n][k]-stored rows -> col-major B fragment (R4-validated)
__device__ __forceinline__ void ldsm2(uint32_t* r, uint32_t a) {
    asm volatile("ldmatrix.sync.aligned.m8n8.x2.shared.b16 {%0,%1}, [%2];"
        : "=r"(r[0]), "=r"(r[1]) : "r"(a));
}
// trans x2: for [k][n]-stored rows (V tile) -> col-major B fragment
__device__ __forceinline__ void ldsm2t(uint32_t* r, uint32_t a) {
    asm volatile("ldmatrix.sync.aligned.m8n8.x2.trans.shared.b16 {%0,%1}, [%2];"
        : "=r"(r[0]), "=r"(r[1]) : "r"(a));
}
__device__ __forceinline__ void mma16816(float* d, const uint32_t* a, const uint32_t* b) {
    asm volatile("mma.sync.aligned.m16n8k16.row.col.f32.bf16.bf16.f32 "
        "{%0,%1,%2,%3}, {%4,%5,%6,%7}, {%8,%9}, {%0,%1,%2,%3};"
        : "+f"(d[0]), "+f"(d[1]), "+f"(d[2]), "+f"(d[3])
        : "r"(a[0]), "r"(a[1]), "r"(a[2]), "r"(a[3]), "r"(b[0]), "r"(b[1]));
}
__device__ __forceinline__ uint32_t packbf2(float a, float b) {
    __nv_bfloat162 h;
    h.x = __float2bfloat16(a); h.y = __float2bfloat16(b);
    return *(uint32_t*)&h;
}

// ---------------------------------------------------------------------------
// fp32 -> bf16 hi/lo split
// ---------------------------------------------------------------------------
__global__ void split_fp32(const float4* __restrict__ src,
                           __nv_bfloat162* __restrict__ hi,
                           __nv_bfloat162* __restrict__ lo, int n4)
{
    int i = blockIdx.x * blockDim.x + threadIdx.x;
    if (i >= n4) return;
    float4 v = src[i];
    __nv_bfloat16 hx = __float2bfloat16(v.x), hy = __float2bfloat16(v.y);
    __nv_bfloat16 hz = __float2bfloat16(v.z), hw = __float2bfloat16(v.w);
    hi[2*i]   = __halves2bfloat162(hx, hy);
    hi[2*i+1] = __halves2bfloat162(hz, hw);
    lo[2*i]   = __halves2bfloat162(__float2bfloat16(v.x - __bfloat162float(hx)),
                                   __float2bfloat16(v.y - __bfloat162float(hy)));
    lo[2*i+1] = __halves2bfloat162(__float2bfloat16(v.z - __bfloat162float(hz)),
                                   __float2bfloat16(v.w - __bfloat162float(hw)));
}

// ---------------------------------------------------------------------------
// transpose + split: W [K=1024][N] fp32 -> hi/lo [N][K=1024] bf16
// ---------------------------------------------------------------------------
__global__ void tsplit_w(const float* __restrict__ src,
                         __nv_bfloat16* __restrict__ hi,
                         __nv_bfloat16* __restrict__ lo, int N)
{
    __shared__ float t[32][33];
    const int n0 = blockIdx.x * 32, k0 = blockIdx.y * 32;
    const int tx = threadIdx.x, ty = threadIdx.y;
    #pragma unroll
    for (int r = ty; r < 32; r += 8)
        t[r][tx] = src[(size_t)(k0 + r) * N + n0 + tx];
    __syncthreads();
    #pragma unroll
    for (int r = ty; r < 32; r += 8) {
        float v = t[tx][r];
        __nv_bfloat16 h = __float2bfloat16(v);
        size_t o = (size_t)(n0 + r) * GK + k0 + tx;
        hi[o] = h;
        lo[o] = __float2bfloat16(v - __bfloat162float(h));
    }
}

// ---------------------------------------------------------------------------
// HMMA GEMM: C = A[M,1024] * B[N,1024]^T via bf16 split (3 mma terms)
// 128x128 tile, BK=32, 8 warps (2x4), 3-stage cp.async pipeline, 1 CTA/SM,
// one barrier per iter, batched ldmatrix with ks-level software pipelining.
// EPI=0: split + scatter into g_{q,k,v}{hi,lo} (Q scaled 0.125)
// EPI=1: +bias -> Cout (fp32)
// ---------------------------------------------------------------------------
#define BK 32
#define MATB (128 * 40 * 2)           // 10240 B per matrix tile (80B rows)
#define STAGEB (4 * MATB)             // 40960 (Ahi, Alo, Bhi, Blo)
#define GEMM_SMEM (3 * STAGEB)        // 122880

template<int EPI>
__global__ __launch_bounds__(256, 1)
void mma_gemm(const __nv_bfloat16* __restrict__ Ahi, const __nv_bfloat16* __restrict__ Alo,
              const __nv_bfloat16* __restrict__ Bhi, const __nv_bfloat16* __restrict__ Blo,
              const float* __restrict__ bias, float* __restrict__ Cout)
{
    extern __shared__ char smc[];
    const uint32_t sb = smem_u32(smc);

    const int tid = threadIdx.x;
    const int wid = tid >> 5, lane = tid & 31;
    const int warp_m = wid >> 2;
    const int warp_n = wid & 3;
    const int m0 = blockIdx.y * 128, n0 = blockIdx.x * 128;
    const int NIT = GK / BK;            // 32

    // issue one k-chunk into stage s; empty commit keeps group counting uniform
    auto issue = [&](int kc, int s) {
        if (kc < NIT) {
            const uint32_t dstb = sb + s * STAGEB;
            #pragma unroll
            for (int i = 0; i < 8; i++) {
                int idx = i * 256 + tid;
                int mtx = idx >> 9;
                int r   = (idx >> 2) & 127;
                int c4  = idx & 3;
                const __nv_bfloat16* p;
                if      (mtx == 0) p = Ahi + (size_t)(m0 + r) * GK;
                else if (mtx == 1) p = Alo + (size_t)(m0 + r) * GK;
                else if (mtx == 2) p = Bhi + (size_t)(n0 + r) * GK;
                else               p = Blo + (size_t)(n0 + r) * GK;
                p += kc * BK + c4 * 8;
                cp16(dstb + mtx * MATB + r * 80 + c4 * 16, p);
            }
        }
        cp_commit();
    };

    float acc[4][4][4];
    #pragma unroll
    for (int a = 0; a < 4; a++)
        #pragma unroll
        for (int b = 0; b < 4; b++)
            #pragma unroll
            for (int c = 0; c < 4; c++) acc[a][b][c] = 0.f;

    // fragment double-buffers (ks-level)
    uint32_t ah[2][4][4], al[2][4][4], bh[2][4][2], bl[2][4][2];

    auto loadfrag = [&](int ks, int buf, uint32_t St) {
        const uint32_t kb = ks * 32 + (lane >> 4) * 16;
        #pragma unroll
        for (int mt = 0; mt < 4; mt++) {
            uint32_t ro = St + (uint32_t)(warp_m * 64 + mt * 16 + (lane & 15)) * 80 + kb;
            ldsm4(ah[buf][mt], ro);
            ldsm4(al[buf][mt], ro + MATB);
        }
        const uint32_t kbb = ks * 32 + ((lane >> 3) & 1) * 16;
        #pragma unroll
        for (int nt = 0; nt < 4; nt++) {
            uint32_t ro = St + 2 * MATB
                        + (uint32_t)(warp_n * 32 + nt * 8 + (lane & 7)) * 80 + kbb;
            ldsm2(bh[buf][nt], ro);
            ldsm2(bl[buf][nt], ro + MATB);
        }
    };
    auto domma = [&](int buf) {
        #pragma unroll
        for (int nt = 0; nt < 4; nt++)
            #pragma unroll
            for (int mt = 0; mt < 4; mt++) {
                mma16816(acc[mt][nt], ah[buf][mt], bh[buf][nt]);
                mma16816(acc[mt][nt], al[buf][mt], bh[buf][nt]);
                mma16816(acc[mt][nt], ah[buf][mt], bl[buf][nt]);
            }
    };

    // prologue: two stages in flight
    issue(0, 0);
    issue(1, 1);

    for (int kc = 0; kc < NIT; kc++) {
        const int s = kc % 3;
        cp_wait<1>();                       // stage kc landed
        __syncthreads();                    // all warps done reading stage (kc-1)%3
        issue(kc + 2, (kc + 2) % 3);        // refill the stage freed at iter kc-1
        const uint32_t St = sb + s * STAGEB;
        loadfrag(0, 0, St);
        loadfrag(1, 1, St);                 // covered by ks0's mma below
        domma(0);
        domma(1);
    }

    const int g = lane >> 2, tg = lane & 3;
    #pragma unroll
    for (int mt = 0; mt < 4; mt++) {
        #pragma unroll
        for (int nt = 0; nt < 4; nt++) {
            const int c  = n0 + warp_n * 32 + nt * 8 + tg * 2;
            const int r0 = m0 + warp_m * 64 + mt * 16 + g;
            #pragma unroll
            for (int h = 0; h < 2; h++) {
                const int r = r0 + h * 8;
                float2 v = make_float2(acc[mt][nt][2*h], acc[mt][nt][2*h+1]);
                if (EPI == 0) {
                    const int bb = r >> 11, t = r & 2047;
                    const int mat = c >> 10, cc = c & 1023;
                    const int head = cc >> 6, d = cc & 63;
                    if (mat == 0) { v.x *= 0.125f; v.y *= 0.125f; }
                    __nv_bfloat16 h0 = __float2bfloat16(v.x), h1 = __float2bfloat16(v.y);
                    __nv_bfloat162 hi2; hi2.x = h0; hi2.y = h1;
                    __nv_bfloat162 lo2;
                    lo2.x = __float2bfloat16(v.x - __bfloat162float(h0));
                    lo2.y = __float2bfloat16(v.y - __bfloat162float(h1));
                    size_t o = (((size_t)(bb * HEADS + head) * TT + t) * HS + d) >> 1;
                    __nv_bfloat162* hp = (mat == 0) ? (__nv_bfloat162*)g_qhi
                                        : (mat == 1) ? (__nv_bfloat162*)g_khi
                                                     : (__nv_bfloat162*)g_vhi;
                    __nv_bfloat162* lp = (mat == 0) ? (__nv_bfloat162*)g_qlo
                                        : (mat == 1) ? (__nv_bfloat162*)g_klo
                                                     : (__nv_bfloat162*)g_vlo;
                    hp[o] = hi2; lp[o] = lo2;
                } else {
                    float2 bv = *(const float2*)(bias + c);
                    v.x += bv.x; v.y += bv.y;
                    *(float2*)(Cout + (size_t)r * EMB + c) = v;
                }
            }
        }
    }
}

// ---------------------------------------------------------------------------
// Tensor-core flash attention (R5-validated, unchanged). BM=128, BN=64, hs=64,
// 8 warps; Q fragments register-resident; K/V hi/lo double-buffered cp.async.
// ---------------------------------------------------------------------------
#define ATILE_B  (64 * 144)            // 9216 B per 64-row tile
#define ASTAGE_B (4 * ATILE_B)         // Khi,Klo,Vhi,Vlo = 36864
#define ATT_SMEM (2 * ASTAGE_B)        // 73728

__global__ __launch_bounds__(256)
void attn_mma()
{
    extern __shared__ char sm[];
    const uint32_t sb = smem_u32(sm);
    const int tid = threadIdx.x, wid = tid >> 5, lane = tid & 31;
    const int qt = gridDim.x - 1 - blockIdx.x;     // heavy tiles first
    const int bh = blockIdx.y;
    const int q0 = qt * 128;
    const int g = lane >> 2, tg = lane & 3;

    // ---- stage Q (hi/lo) into smem, then ldmatrix to registers ----
    {
        const __nv_bfloat16* Qh = g_qhi + ((size_t)bh * TT + q0) * HS;
        const __nv_bfloat16* Ql = g_qlo + ((size_t)bh * TT + q0) * HS;
        #pragma unroll
        for (int i = 0; i < 8; i++) {
            int idx = i * 256 + tid;               // 0..2047
            int mtx = idx >> 10;                   // 0 hi, 1 lo
            int r = (idx >> 3) & 127, c8 = idx & 7;
            const __nv_bfloat16* src = (mtx ? Ql : Qh) + r * HS + c8 * 8;
            *(uint4*)(sm + mtx * 18432 + r * 144 + c8 * 16) = *(const uint4*)src;
        }
    }
    __syncthreads();
    uint32_t qh[4][4], ql[4][4];
    #pragma unroll
    for (int kg = 0; kg < 4; kg++) {
        uint32_t a = sb + (uint32_t)(wid * 16 + (lane & 15)) * 144 + kg * 32 + (lane >> 4) * 16;
        ldsm4(qh[kg], a);
        ldsm4(ql[kg], a + 18432);
    }
    __syncthreads();

    // ---- K/V pipeline ----
    auto issueKV = [&](int kt, int s) {
        const uint32_t dstb = sb + s * ASTAGE_B;
        const size_t rowb = ((size_t)bh * TT + kt * 64) * HS;
        #pragma unroll
        for (int i = 0; i < 8; i++) {
            int idx = i * 256 + tid;               // 0..2047
            int mtx = idx >> 9;                    // 0 Khi 1 Klo 2 Vhi 3 Vlo
            int r = (idx >> 3) & 63, c8 = idx & 7;
            const __nv_bfloat16* p =
                (mtx == 0 ? g_khi : mtx == 1 ? g_klo : mtx == 2 ? g_vhi : g_vlo)
                + rowb + r * HS + c8 * 8;
            cp16(dstb + mtx * ATILE_B + r * 144 + c8 * 16, p);
        }
        cp_commit();
    };

    float oacc[8][4];
    #pragma unroll
    for (int nt = 0; nt < 8; nt++)
        #pragma unroll
        for (int c = 0; c < 4; c++) oacc[nt][c] = 0.f;
    float mrow[2] = {-1e30f, -1e30f}, lrow[2] = {0.f, 0.f};

    const int dq = (q0 + wid * 16) >> 6;           // warp's diagonal 64-tile
    const int ktmax = 2 * qt + 1;

    issueKV(0, 0);
    for (int kt = 0; kt <= ktmax; kt++) {
        const int s = kt & 1;
        if (kt < ktmax) { issueKV(kt + 1, s ^ 1); cp_wait<1>(); }
        else            { cp_wait<0>(); }
        __syncthreads();

        if (kt <= dq) {
            const uint32_t base = sb + s * ASTAGE_B;

            // S = Q K^T  (3-term split)
            float sacc[8][4];
            #pragma unroll
            for (int nt = 0; nt < 8; nt++)
                #pragma unroll
                for (int c = 0; c < 4; c++) sacc[nt][c] = 0.f;

            #pragma unroll
            for (int kg = 0; kg < 4; kg++) {
                #pragma unroll
                for (int nt = 0; nt < 8; nt++) {
                    uint32_t ro = base + (uint32_t)(nt * 8 + (lane & 7)) * 144
                                 + kg * 32 + ((lane >> 3) & 1) * 16;
                    uint32_t kbh[2], kbl[2];
                    ldsm2(kbh, ro);
                    ldsm2(kbl, ro + ATILE_B);
                    mma16816(sacc[nt], qh[kg], kbh);
                    mma16816(sacc[nt], ql[kg], kbh);
                    mma16816(sacc[nt], qh[kg], kbl);
                }
            }

            // causal mask on the diagonal tile
            if (kt == dq) {
                const int rl = ((q0 + wid * 16) & 63) + g;
                #pragma unroll
                for (int nt = 0; nt < 8; nt++) {
                    int c0 = nt * 8 + tg * 2;
                    if (c0     > rl)     sacc[nt][0] = -1e30f;
                    if (c0 + 1 > rl)     sacc[nt][1] = -1e30f;
                    if (c0     > rl + 8) sacc[nt][2] = -1e30f;
                    if (c0 + 1 > rl + 8) sacc[nt][3] = -1e30f;
                }
            }

            // online softmax (rows g, g+8; quad reduction over tg)
            #pragma unroll
            for (int r = 0; r < 2; r++) {
                float mx = -1e30f;
                #pragma unroll
                for (int nt = 0; nt < 8; nt++)
                    mx = fmaxf(mx, fmaxf(sacc[nt][2*r], sacc[nt][2*r+1]));
                mx = fmaxf(mx, __shfl_xor_sync(0xffffffffu, mx, 1));
                mx = fmaxf(mx, __shfl_xor_sync(0xffffffffu, mx, 2));
                float mnew = fmaxf(mrow[r], mx);
                float corr = __expf(mrow[r] - mnew);
                float rs = 0.f;
                #pragma unroll
                for (int nt = 0; nt < 8; nt++) {
                    float p0 = __expf(sacc[nt][2*r]   - mnew);
                    float p1 = __expf(sacc[nt][2*r+1] - mnew);
                    sacc[nt][2*r] = p0; sacc[nt][2*r+1] = p1;
                    rs += p0 + p1;
                }
                rs += __shfl_xor_sync(0xffffffffu, rs, 1);
                rs += __shfl_xor_sync(0xffffffffu, rs, 2);
                lrow[r] = lrow[r] * corr + rs;
                mrow[r] = mnew;
                #pragma unroll
                for (int nt = 0; nt < 8; nt++) {
                    oacc[nt][2*r] *= corr; oacc[nt][2*r+1] *= corr;
                }
            }

            // O += P V  (P hi/lo from S fragments; V via ldmatrix.trans)
            #pragma unroll
            for (int kg = 0; kg < 4; kg++) {
                uint32_t ph[4], pl[4];
                #pragma unroll
                for (int q = 0; q < 4; q++) {
                    float a = sacc[2*kg + (q >> 1)][(q & 1) * 2];
                    float b = sacc[2*kg + (q >> 1)][(q & 1) * 2 + 1];
                    ph[q] = packbf2(a, b);
                    __nv_bfloat162 hh = *(__nv_bfloat162*)&ph[q];
                    pl[q] = packbf2(a - __bfloat162float(hh.x),
                                    b - __bfloat162float(hh.y));
                }
                #pragma unroll
                for (int nt = 0; nt < 8; nt++) {
                    uint32_t ro = base + 2 * ATILE_B
                                 + (uint32_t)(kg * 16 + (lane & 15)) * 144 + nt * 16;
                    uint32_t vbh[2], vbl[2];
                    ldsm2t(vbh, ro);
                    ldsm2t(vbl, ro + ATILE_B);
                    mma16816(oacc[nt], ph, vbh);
                    mma16816(oacc[nt], pl, vbh);
                    mma16816(oacc[nt], ph, vbl);
                }
            }
        }
        __syncthreads();
    }

    // epilogue: write hi/lo bf16 directly as the proj-GEMM A operand
    const int b = bh >> 4, h = bh & 15;
    #pragma unroll
    for (int r = 0; r < 2; r++) {
        float inv = 1.0f / lrow[r];
        int t = q0 + wid * 16 + g + r * 8;
        size_t rowo = ((size_t)(b * TT + t)) * EMB + h * HS;
        #pragma unroll
        for (int nt = 0; nt < 8; nt++) {
            float o0 = oacc[nt][2*r] * inv, o1 = oacc[nt][2*r+1] * inv;
            __nv_bfloat16 h0 = __float2bfloat16(o0), h1 = __float2bfloat16(o1);
            __nv_bfloat162 hi2; hi2.x = h0; hi2.y = h1;
            __nv_bfloat162 lo2;
            lo2.x = __float2bfloat16(o0 - __bfloat162float(h0));
            lo2.y = __float2bfloat16(o1 - __bfloat162float(h1));
            size_t o = (rowo + nt * 8 + tg * 2) >> 1;
            ((__nv_bfloat162*)g_ahi)[o] = hi2;
            ((__nv_bfloat162*)g_alo)[o] = lo2;
        }
    }
}

// ---------------------------------------------------------------------------
extern "C" void kernel_launch(void* const* d_in, const int* in_sizes, int n_in,
                              void* d_out, int out_size)
{
    const float* x      = (const float*)d_in[0];
    const float* w_qkv  = (const float*)d_in[1];
    const float* w_proj = (const float*)d_in[2];
    const float* b_proj = (const float*)d_in[3];
    float* out = (float*)d_out;

    cudaFuncSetAttribute(attn_mma, cudaFuncAttributeMaxDynamicSharedMemorySize, ATT_SMEM);
    cudaFuncSetAttribute(mma_gemm<0>, cudaFuncAttributeMaxDynamicSharedMemorySize, GEMM_SMEM);
    cudaFuncSetAttribute(mma_gemm<1>, cudaFuncAttributeMaxDynamicSharedMemorySize, GEMM_SMEM);

    __nv_bfloat16 *xhi, *xlo, *ahi, *alo, *wqhi, *wqlo, *wphi, *wplo;
    cudaGetSymbolAddress((void**)&xhi,  g_xhi);
    cudaGetSymbolAddress((void**)&xlo,  g_xlo);
    cudaGetSymbolAddress((void**)&ahi,  g_ahi);
    cudaGetSymbolAddress((void**)&alo,  g_alo);
    cudaGetSymbolAddress((void**)&wqhi, g_wqhi);
    cudaGetSymbolAddress((void**)&wqlo, g_wqlo);
    cudaGetSymbolAddress((void**)&wphi, g_wphi);
    cudaGetSymbolAddress((void**)&wplo, g_wplo);

    // 1. split x -> bf16 hi/lo
    split_fp32<<<(NROWS * GK / 4 + 255) / 256, 256>>>(
        (const float4*)x, (__nv_bfloat162*)xhi, (__nv_bfloat162*)xlo, NROWS * GK / 4);

    // 2. transpose+split weights
    tsplit_w<<<dim3(3 * EMB / 32, GK / 32), dim3(32, 8)>>>(w_qkv, wqhi, wqlo, 3 * EMB);
    tsplit_w<<<dim3(EMB / 32, GK / 32), dim3(32, 8)>>>(w_proj, wphi, wplo, EMB);

    // 3. QKV GEMM (HMMA, 3-stage) -> bf16 hi/lo q/k/v (Q pre-scaled)
    mma_gemm<0><<<dim3(3 * EMB / 128, NROWS / 128), 256, GEMM_SMEM>>>(
        xhi, xlo, wqhi, wqlo, nullptr, nullptr);

    // 4. tensor-core causal flash attention -> g_ahi/g_alo
    attn_mma<<<dim3(TT / 128, BB * HEADS), 256, ATT_SMEM>>>();

    // 5. output projection (HMMA, 3-stage) + bias
    mma_gemm<1><<<dim3(EMB / 128, NROWS / 128), 256, GEMM_SMEM>>>(
        ahi, alo, wphi, wplo, b_proj, out);
}

// round 7
// speedup vs baseline: 1.4917x; 1.4917x over previous
#include <cuda_runtime.h>
#include <cuda_fp16.h>
#include <cstdint>
#include <math.h>

// Problem constants
#define BB 2
#define TT 2048
#define EMB 1024
#define HEADS 16
#define HS 64
#define NROWS (BB*TT)          // 4096
#define GK 1024                // K for both GEMMs

// ---------------------------------------------------------------------------
// Scratch (__device__ globals; allocation-free rule)
// fp16 2-term: activations split hi/lo, weights & K/V hi only.
// ---------------------------------------------------------------------------
__device__ __half g_qhi[(size_t)BB*HEADS*TT*HS];   // [bh][t][d], pre-scaled 0.125
__device__ __half g_qlo[(size_t)BB*HEADS*TT*HS];
__device__ __half g_khi[(size_t)BB*HEADS*TT*HS];
__device__ __half g_vhi[(size_t)BB*HEADS*TT*HS];

__device__ __half g_xhi[(size_t)NROWS*GK];
__device__ __half g_xlo[(size_t)NROWS*GK];
__device__ __half g_ahi[(size_t)NROWS*GK];         // attention out (proj input)
__device__ __half g_alo[(size_t)NROWS*GK];
__device__ __half g_wqhi[(size_t)3*EMB*GK];        // [3072][1024] K-major
__device__ __half g_wphi[(size_t)EMB*GK];          // [1024][1024] K-major

// ---------------------------------------------------------------------------
// PTX helpers (portable sm_80+ subset: ldmatrix / mma.sync / cp.async)
// ---------------------------------------------------------------------------
__device__ __forceinline__ uint32_t smem_u32(const void* p) {
    uint32_t a;
    asm("{ .reg .u64 t; cvta.to.shared.u64 t, %1; cvt.u32.u64 %0, t; }" : "=r"(a) : "l"(p));
    return a;
}
__device__ __forceinline__ void cp16(uint32_t dst, const void* src) {
    asm volatile("cp.async.cg.shared.global [%0], [%1], 16;" :: "r"(dst), "l"(src));
}
__device__ __forceinline__ void cp_commit() {
    asm volatile("cp.async.commit_group;" ::: "memory");
}
template<int N>
__device__ __forceinline__ void cp_wait() {
    asm volatile("cp.async.wait_group %0;" :: "n"(N) : "memory");
}
__device__ __forceinline__ void ldsm4(uint32_t* r, uint32_t a) {
    asm volatile("ldmatrix.sync.aligned.m8n8.x4.shared.b16 {%0,%1,%2,%3}, [%4];"
        : "=r"(r[0]), "=r"(r[1]), "=r"(r[2]), "=r"(r[3]) : "r"(a));
}
// non-trans x2: [n][k]-stored rows -> col-major B fragment (R4-validated)
__device__ __forceinline__ void ldsm2(uint32_t* r, uint32_t a) {
    asm volatile("ldmatrix.sync.aligned.m8n8.x2.shared.b16 {%0,%1}, [%2];"
        : "=r"(r[0]), "=r"(r[1]) : "r"(a));
}
// trans x2: [k][n]-stored rows (V tile) -> col-major B fragment (R5-validated)
__device__ __forceinline__ void ldsm2t(uint32_t* r, uint32_t a) {
    asm volatile("ldmatrix.sync.aligned.m8n8.x2.trans.shared.b16 {%0,%1}, [%2];"
        : "=r"(r[0]), "=r"(r[1]) : "r"(a));
}
__device__ __forceinline__ void mma16816(float* d, const uint32_t* a, const uint32_t* b) {
    asm volatile("mma.sync.aligned.m16n8k16.row.col.f32.f16.f16.f32 "
        "{%0,%1,%2,%3}, {%4,%5,%6,%7}, {%8,%9}, {%0,%1,%2,%3};"
        : "+f"(d[0]), "+f"(d[1]), "+f"(d[2]), "+f"(d[3])
        : "r"(a[0]), "r"(a[1]), "r"(a[2]), "r"(a[3]), "r"(b[0]), "r"(b[1]));
}
__device__ __forceinline__ uint32_t packh2(float a, float b) {
    __half2 h = __floats2half2_rn(a, b);
    return *(uint32_t*)&h;
}

// ---------------------------------------------------------------------------
// fp32 -> fp16 hi/lo split (activations)
// ---------------------------------------------------------------------------
__global__ void split_fp32(const float4* __restrict__ src,
                           __half2* __restrict__ hi,
                           __half2* __restrict__ lo, int n4)
{
    int i = blockIdx.x * blockDim.x + threadIdx.x;
    if (i >= n4) return;
    float4 v = src[i];
    __half hx = __float2half(v.x), hy = __float2half(v.y);
    __half hz = __float2half(v.z), hw = __float2half(v.w);
    hi[2*i]   = __halves2half2(hx, hy);
    hi[2*i+1] = __halves2half2(hz, hw);
    lo[2*i]   = __halves2half2(__float2half(v.x - __half2float(hx)),
                               __float2half(v.y - __half2float(hy)));
    lo[2*i+1] = __halves2half2(__float2half(v.z - __half2float(hz)),
                               __float2half(v.w - __half2float(hw)));
}

// ---------------------------------------------------------------------------
// transpose: W [K=1024][N] fp32 -> hi [N][K=1024] fp16 (no lo needed, 2-term)
// ---------------------------------------------------------------------------
__global__ void tsplit_w(const float* __restrict__ src,
                         __half* __restrict__ hi, int N)
{
    __shared__ float t[32][33];
    const int n0 = blockIdx.x * 32, k0 = blockIdx.y * 32;
    const int tx = threadIdx.x, ty = threadIdx.y;
    #pragma unroll
    for (int r = ty; r < 32; r += 8)
        t[r][tx] = src[(size_t)(k0 + r) * N + n0 + tx];
    __syncthreads();
    #pragma unroll
    for (int r = ty; r < 32; r += 8)
        hi[(size_t)(n0 + r) * GK + k0 + tx] = __float2half(t[tx][r]);
}

// ---------------------------------------------------------------------------
// HMMA GEMM: C = A[M,1024] * B[N,1024]^T,  fp16 2-term: (Ah+Al)*Bh
// 128x128 tile, BK=32, 8 warps (2x4), cp.async double buffer, 2 CTA/SM.
// Stage: Ahi, Alo, Bhi tiles (80B rows -> conflict-free ldmatrix).
// EPI=0: scatter into g_qhi/g_qlo (x0.125), g_khi, g_vhi
// EPI=1: +bias -> Cout (fp32)
// ---------------------------------------------------------------------------
#define BK 32
#define MATB (128 * 40 * 2)           // 10240 B per matrix tile (80B rows)
#define STAGEB (3 * MATB)             // 30720 (Ahi, Alo, Bhi)
#define GEMM_SMEM (2 * STAGEB)        // 61440

template<int EPI>
__global__ __launch_bounds__(256, 2)
void mma_gemm(const __half* __restrict__ Ahi, const __half* __restrict__ Alo,
              const __half* __restrict__ Bhi,
              const float* __restrict__ bias, float* __restrict__ Cout)
{
    extern __shared__ char smc[];
    const uint32_t sb = smem_u32(smc);

    const int tid = threadIdx.x;
    const int wid = tid >> 5, lane = tid & 31;
    const int warp_m = wid >> 2;      // 0..1
    const int warp_n = wid & 3;       // 0..3
    const int m0 = blockIdx.y * 128, n0 = blockIdx.x * 128;

    // async loader: 1536 16B chunks per stage, 6 per thread
    auto issue = [&](int kc, int s) {
        const uint32_t dstb = sb + s * STAGEB;
        #pragma unroll
        for (int i = 0; i < 6; i++) {
            int idx = i * 256 + tid;            // 0..1535
            int mtx = idx >> 9;                 // 0:Ahi 1:Alo 2:Bhi
            int r   = (idx >> 2) & 127;
            int c4  = idx & 3;
            const __half* p;
            if      (mtx == 0) p = Ahi + (size_t)(m0 + r) * GK;
            else if (mtx == 1) p = Alo + (size_t)(m0 + r) * GK;
            else               p = Bhi + (size_t)(n0 + r) * GK;
            p += kc * BK + c4 * 8;
            cp16(dstb + mtx * MATB + r * 80 + c4 * 16, p);
        }
        cp_commit();
    };

    float acc[4][4][4];
    #pragma unroll
    for (int a = 0; a < 4; a++)
        #pragma unroll
        for (int b = 0; b < 4; b++)
            #pragma unroll
            for (int c = 0; c < 4; c++) acc[a][b][c] = 0.f;

    issue(0, 0);
    const int NIT = GK / BK;            // 32
    for (int kc = 0; kc < NIT; kc++) {
        const int s = kc & 1;
        if (kc + 1 < NIT) { issue(kc + 1, s ^ 1); cp_wait<1>(); }
        else              { cp_wait<0>(); }
        __syncthreads();

        const uint32_t Ah = sb + s * STAGEB;
        const uint32_t Al = Ah + MATB;
        const uint32_t Bh = Ah + 2 * MATB;

        #pragma unroll
        for (int ks = 0; ks < 2; ks++) {
            const uint32_t kb = ks * 32 + (lane >> 4) * 16;
            uint32_t ah[4][4], al[4][4];
            #pragma unroll
            for (int mt = 0; mt < 4; mt++) {
                uint32_t ro = (uint32_t)(warp_m * 64 + mt * 16 + (lane & 15)) * 80 + kb;
                ldsm4(ah[mt], Ah + ro);
                ldsm4(al[mt], Al + ro);
            }
            const uint32_t kbb = ks * 32 + ((lane >> 3) & 1) * 16;
            #pragma unroll
            for (int nt = 0; nt < 4; nt++) {
                uint32_t ro = (uint32_t)(warp_n * 32 + nt * 8 + (lane & 7)) * 80 + kbb;
                uint32_t bh[2];
                ldsm2(bh, Bh + ro);
                #pragma unroll
                for (int mt = 0; mt < 4; mt++) {
                    mma16816(acc[mt][nt], ah[mt], bh);
                    mma16816(acc[mt][nt], al[mt], bh);
                }
            }
        }
        __syncthreads();
    }

    const int g = lane >> 2, tg = lane & 3;
    #pragma unroll
    for (int mt = 0; mt < 4; mt++) {
        #pragma unroll
        for (int nt = 0; nt < 4; nt++) {
            const int c  = n0 + warp_n * 32 + nt * 8 + tg * 2;
            const int r0 = m0 + warp_m * 64 + mt * 16 + g;
            #pragma unroll
            for (int h = 0; h < 2; h++) {
                const int r = r0 + h * 8;
                float2 v = make_float2(acc[mt][nt][2*h], acc[mt][nt][2*h+1]);
                if (EPI == 0) {
                    const int bb = r >> 11, t = r & 2047;
                    const int mat = c >> 10, cc = c & 1023;
                    const int head = cc >> 6, d = cc & 63;
                    size_t o = (((size_t)(bb * HEADS + head) * TT + t) * HS + d) >> 1;
                    if (mat == 0) {
                        v.x *= 0.125f; v.y *= 0.125f;
                        __half h0 = __float2half(v.x), h1 = __float2half(v.y);
                        ((__half2*)g_qhi)[o] = __halves2half2(h0, h1);
                        ((__half2*)g_qlo)[o] =
                            __halves2half2(__float2half(v.x - __half2float(h0)),
                                           __float2half(v.y - __half2float(h1)));
                    } else if (mat == 1) {
                        ((__half2*)g_khi)[o] = __floats2half2_rn(v.x, v.y);
                    } else {
                        ((__half2*)g_vhi)[o] = __floats2half2_rn(v.x, v.y);
                    }
                } else {
                    float2 bv = *(const float2*)(bias + c);
                    v.x += bv.x; v.y += bv.y;
                    *(float2*)(Cout + (size_t)r * EMB + c) = v;
                }
            }
        }
    }
}

// ---------------------------------------------------------------------------
// Tensor-core flash attention, fp16 2-term. BM=128, BN=64, hs=64, 8 warps.
// Q hi/lo register-resident; K/V hi-only double-buffered cp.async (144B rows).
// S = (Qh+Ql)Kh ; O += (Ph+Pl)Vh. Causal per-warp tile classification.
// ---------------------------------------------------------------------------
#define ATILE_B  (64 * 144)            // 9216 B per 64-row tile
#define ASTAGE_B (2 * ATILE_B)         // Khi, Vhi = 18432
#define ATT_SMEM (2 * ASTAGE_B)        // 36864 (also fits Q hi/lo staging)

__global__ __launch_bounds__(256)
void attn_mma()
{
    extern __shared__ char sm[];
    const uint32_t sb = smem_u32(sm);
    const int tid = threadIdx.x, wid = tid >> 5, lane = tid & 31;
    const int qt = gridDim.x - 1 - blockIdx.x;     // heavy tiles first
    const int bh = blockIdx.y;
    const int q0 = qt * 128;
    const int g = lane >> 2, tg = lane & 3;

    // ---- stage Q (hi/lo) into smem, then ldmatrix to registers ----
    {
        const __half* Qh = g_qhi + ((size_t)bh * TT + q0) * HS;
        const __half* Ql = g_qlo + ((size_t)bh * TT + q0) * HS;
        #pragma unroll
        for (int i = 0; i < 8; i++) {
            int idx = i * 256 + tid;               // 0..2047
            int mtx = idx >> 10;                   // 0 hi, 1 lo
            int r = (idx >> 3) & 127, c8 = idx & 7;
            const __half* src = (mtx ? Ql : Qh) + r * HS + c8 * 8;
            *(uint4*)(sm + mtx * 18432 + r * 144 + c8 * 16) = *(const uint4*)src;
        }
    }
    __syncthreads();
    uint32_t qh[4][4], ql[4][4];
    #pragma unroll
    for (int kg = 0; kg < 4; kg++) {
        uint32_t a = sb + (uint32_t)(wid * 16 + (lane & 15)) * 144 + kg * 32 + (lane >> 4) * 16;
        ldsm4(qh[kg], a);
        ldsm4(ql[kg], a + 18432);
    }
    __syncthreads();

    // ---- K/V pipeline (hi only) ----
    auto issueKV = [&](int kt, int s) {
        const uint32_t dstb = sb + s * ASTAGE_B;
        const size_t rowb = ((size_t)bh * TT + kt * 64) * HS;
        #pragma unroll
        for (int i = 0; i < 4; i++) {
            int idx = i * 256 + tid;               // 0..1023
            int mtx = idx >> 9;                    // 0 Khi 1 Vhi
            int r = (idx >> 3) & 63, c8 = idx & 7;
            const __half* p = (mtx == 0 ? g_khi : g_vhi) + rowb + r * HS + c8 * 8;
            cp16(dstb + mtx * ATILE_B + r * 144 + c8 * 16, p);
        }
        cp_commit();
    };

    float oacc[8][4];
    #pragma unroll
    for (int nt = 0; nt < 8; nt++)
        #pragma unroll
        for (int c = 0; c < 4; c++) oacc[nt][c] = 0.f;
    float mrow[2] = {-1e30f, -1e30f}, lrow[2] = {0.f, 0.f};

    const int dq = (q0 + wid * 16) >> 6;           // warp's diagonal 64-tile
    const int ktmax = 2 * qt + 1;

    issueKV(0, 0);
    for (int kt = 0; kt <= ktmax; kt++) {
        const int s = kt & 1;
        if (kt < ktmax) { issueKV(kt + 1, s ^ 1); cp_wait<1>(); }
        else            { cp_wait<0>(); }
        __syncthreads();

        if (kt <= dq) {
            const uint32_t base = sb + s * ASTAGE_B;

            // S = Q K^T  (2-term: (Qh+Ql)·Kh)
            float sacc[8][4];
            #pragma unroll
            for (int nt = 0; nt < 8; nt++)
                #pragma unroll
                for (int c = 0; c < 4; c++) sacc[nt][c] = 0.f;

            #pragma unroll
            for (int kg = 0; kg < 4; kg++) {
                #pragma unroll
                for (int nt = 0; nt < 8; nt++) {
                    uint32_t ro = base + (uint32_t)(nt * 8 + (lane & 7)) * 144
                                 + kg * 32 + ((lane >> 3) & 1) * 16;
                    uint32_t kbh[2];
                    ldsm2(kbh, ro);
                    mma16816(sacc[nt], qh[kg], kbh);
                    mma16816(sacc[nt], ql[kg], kbh);
                }
            }

            // causal mask on the diagonal tile
            if (kt == dq) {
                const int rl = ((q0 + wid * 16) & 63) + g;
                #pragma unroll
                for (int nt = 0; nt < 8; nt++) {
                    int c0 = nt * 8 + tg * 2;
                    if (c0     > rl)     sacc[nt][0] = -1e30f;
                    if (c0 + 1 > rl)     sacc[nt][1] = -1e30f;
                    if (c0     > rl + 8) sacc[nt][2] = -1e30f;
                    if (c0 + 1 > rl + 8) sacc[nt][3] = -1e30f;
                }
            }

            // online softmax (rows g, g+8; quad reduction over tg)
            #pragma unroll
            for (int r = 0; r < 2; r++) {
                float mx = -1e30f;
                #pragma unroll
                for (int nt = 0; nt < 8; nt++)
                    mx = fmaxf(mx, fmaxf(sacc[nt][2*r], sacc[nt][2*r+1]));
                mx = fmaxf(mx, __shfl_xor_sync(0xffffffffu, mx, 1));
                mx = fmaxf(mx, __shfl_xor_sync(0xffffffffu, mx, 2));
                float mnew = fmaxf(mrow[r], mx);
                float corr = __expf(mrow[r] - mnew);
                float rs = 0.f;
                #pragma unroll
                for (int nt = 0; nt < 8; nt++) {
                    float p0 = __expf(sacc[nt][2*r]   - mnew);
                    float p1 = __expf(sacc[nt][2*r+1] - mnew);
                    sacc[nt][2*r] = p0; sacc[nt][2*r+1] = p1;
                    rs += p0 + p1;
                }
                rs += __shfl_xor_sync(0xffffffffu, rs, 1);
                rs += __shfl_xor_sync(0xffffffffu, rs, 2);
                lrow[r] = lrow[r] * corr + rs;
                mrow[r] = mnew;
                #pragma unroll
                for (int nt = 0; nt < 8; nt++) {
                    oacc[nt][2*r] *= corr; oacc[nt][2*r+1] *= corr;
                }
            }

            // O += P V  (2-term: (Ph+Pl)·Vh; V via ldmatrix.trans)
            #pragma unroll
            for (int kg = 0; kg < 4; kg++) {
                uint32_t ph[4], pl[4];
                #pragma unroll
                for (int q = 0; q < 4; q++) {
                    float a = sacc[2*kg + (q >> 1)][(q & 1) * 2];
                    float b = sacc[2*kg + (q >> 1)][(q & 1) * 2 + 1];
                    ph[q] = packh2(a, b);
                    __half2 hh = *(__half2*)&ph[q];
                    pl[q] = packh2(a - __half2float(hh.x),
                                   b - __half2float(hh.y));
                }
                #pragma unroll
                for (int nt = 0; nt < 8; nt++) {
                    uint32_t ro = base + ATILE_B
                                 + (uint32_t)(kg * 16 + (lane & 15)) * 144 + nt * 16;
                    uint32_t vbh[2];
                    ldsm2t(vbh, ro);
                    mma16816(oacc[nt], ph, vbh);
                    mma16816(oacc[nt], pl, vbh);
                }
            }
        }
        __syncthreads();
    }

    // epilogue: write hi/lo fp16 directly as the proj-GEMM A operand
    const int b = bh >> 4, h = bh & 15;
    #pragma unroll
    for (int r = 0; r < 2; r++) {
        float inv = 1.0f / lrow[r];
        int t = q0 + wid * 16 + g + r * 8;
        size_t rowo = ((size_t)(b * TT + t)) * EMB + h * HS;
        #pragma unroll
        for (int nt = 0; nt < 8; nt++) {
            float o0 = oacc[nt][2*r] * inv, o1 = oacc[nt][2*r+1] * inv;
            __half h0 = __float2half(o0), h1 = __float2half(o1);
            size_t o = (rowo + nt * 8 + tg * 2) >> 1;
            ((__half2*)g_ahi)[o] = __halves2half2(h0, h1);
            ((__half2*)g_alo)[o] =
                __halves2half2(__float2half(o0 - __half2float(h0)),
                               __float2half(o1 - __half2float(h1)));
        }
    }
}

// ---------------------------------------------------------------------------
extern "C" void kernel_launch(void* const* d_in, const int* in_sizes, int n_in,
                              void* d_out, int out_size)
{
    const float* x      = (const float*)d_in[0];
    const float* w_qkv  = (const float*)d_in[1];
    const float* w_proj = (const float*)d_in[2];
    const float* b_proj = (const float*)d_in[3];
    float* out = (float*)d_out;

    cudaFuncSetAttribute(attn_mma, cudaFuncAttributeMaxDynamicSharedMemorySize, ATT_SMEM);
    cudaFuncSetAttribute(mma_gemm<0>, cudaFuncAttributeMaxDynamicSharedMemorySize, GEMM_SMEM);
    cudaFuncSetAttribute(mma_gemm<1>, cudaFuncAttributeMaxDynamicSharedMemorySize, GEMM_SMEM);

    __half *xhi, *xlo, *ahi, *alo, *wqhi, *wphi;
    cudaGetSymbolAddress((void**)&xhi,  g_xhi);
    cudaGetSymbolAddress((void**)&xlo,  g_xlo);
    cudaGetSymbolAddress((void**)&ahi,  g_ahi);
    cudaGetSymbolAddress((void**)&alo,  g_alo);
    cudaGetSymbolAddress((void**)&wqhi, g_wqhi);
    cudaGetSymbolAddress((void**)&wphi, g_wphi);

    // 1. split x -> fp16 hi/lo
    split_fp32<<<(NROWS * GK / 4 + 255) / 256, 256>>>(
        (const float4*)x, (__half2*)xhi, (__half2*)xlo, NROWS * GK / 4);

    // 2. transpose weights to fp16 hi (no lo needed for 2-term)
    tsplit_w<<<dim3(3 * EMB / 32, GK / 32), dim3(32, 8)>>>(w_qkv, wqhi, 3 * EMB);
    tsplit_w<<<dim3(EMB / 32, GK / 32), dim3(32, 8)>>>(w_proj, wphi, EMB);

    // 3. QKV GEMM (fp16 2-term) -> q hi/lo (scaled), k hi, v hi
    mma_gemm<0><<<dim3(3 * EMB / 128, NROWS / 128), 256, GEMM_SMEM>>>(
        xhi, xlo, wqhi, nullptr, nullptr);

    // 4. tensor-core causal flash attention -> g_ahi/g_alo
    attn_mma<<<dim3(TT / 128, BB * HEADS), 256, ATT_SMEM>>>();

    // 5. output projection (fp16 2-term) + bias
    mma_gemm<1><<<dim3(EMB / 128, NROWS / 128), 256, GEMM_SMEM>>>(
        ahi, alo, wphi, b_proj, out);
}

// round 8
// speedup vs baseline: 2.3944x; 1.6052x over previous
#include <cuda_runtime.h>
#include <cuda_fp16.h>
#include <cstdint>
#include <math.h>

// Problem constants
#define BB 2
#define TT 2048
#define EMB 1024
#define HEADS 16
#define HS 64
#define NROWS (BB*TT)          // 4096
#define GK 1024                // K for both GEMMs

// ---------------------------------------------------------------------------
// Scratch (__device__ globals; allocation-free rule). 1-term fp16 everywhere.
// ---------------------------------------------------------------------------
__device__ __half g_qhi[(size_t)BB*HEADS*TT*HS];   // [bh][t][d], pre-scaled 0.125
__device__ __half g_khi[(size_t)BB*HEADS*TT*HS];
__device__ __half g_vhi[(size_t)BB*HEADS*TT*HS];

__device__ __half g_xhi[(size_t)NROWS*GK];
__device__ __half g_ahi[(size_t)NROWS*GK];         // attention out (proj input)
__device__ __half g_wqhi[(size_t)3*EMB*GK];        // [3072][1024] K-major
__device__ __half g_wphi[(size_t)EMB*GK];          // [1024][1024] K-major

// ---------------------------------------------------------------------------
// PTX helpers (portable sm_80+ subset: ldmatrix / mma.sync / cp.async)
// ---------------------------------------------------------------------------
__device__ __forceinline__ uint32_t smem_u32(const void* p) {
    uint32_t a;
    asm("{ .reg .u64 t; cvta.to.shared.u64 t, %1; cvt.u32.u64 %0, t; }" : "=r"(a) : "l"(p));
    return a;
}
__device__ __forceinline__ void cp16(uint32_t dst, const void* src) {
    asm volatile("cp.async.cg.shared.global [%0], [%1], 16;" :: "r"(dst), "l"(src));
}
__device__ __forceinline__ void cp_commit() {
    asm volatile("cp.async.commit_group;" ::: "memory");
}
template<int N>
__device__ __forceinline__ void cp_wait() {
    asm volatile("cp.async.wait_group %0;" :: "n"(N) : "memory");
}
__device__ __forceinline__ void ldsm4(uint32_t* r, uint32_t a) {
    asm volatile("ldmatrix.sync.aligned.m8n8.x4.shared.b16 {%0,%1,%2,%3}, [%4];"
        : "=r"(r[0]), "=r"(r[1]), "=r"(r[2]), "=r"(r[3]) : "r"(a));
}
// non-trans x2: [n][k]-stored rows -> col-major B fragment (R4-validated)
__device__ __forceinline__ void ldsm2(uint32_t* r, uint32_t a) {
    asm volatile("ldmatrix.sync.aligned.m8n8.x2.shared.b16 {%0,%1}, [%2];"
        : "=r"(r[0]), "=r"(r[1]) : "r"(a));
}
// trans x2: [k][n]-stored rows (V tile) -> col-major B fragment (R5-validated)
__device__ __forceinline__ void ldsm2t(uint32_t* r, uint32_t a) {
    asm volatile("ldmatrix.sync.aligned.m8n8.x2.trans.shared.b16 {%0,%1}, [%2];"
        : "=r"(r[0]), "=r"(r[1]) : "r"(a));
}
__device__ __forceinline__ void mma16816(float* d, const uint32_t* a, const uint32_t* b) {
    asm volatile("mma.sync.aligned.m16n8k16.row.col.f32.f16.f16.f32 "
        "{%0,%1,%2,%3}, {%4,%5,%6,%7}, {%8,%9}, {%0,%1,%2,%3};"
        : "+f"(d[0]), "+f"(d[1]), "+f"(d[2]), "+f"(d[3])
        : "r"(a[0]), "r"(a[1]), "r"(a[2]), "r"(a[3]), "r"(b[0]), "r"(b[1]));
}
__device__ __forceinline__ uint32_t packh2(float a, float b) {
    __half2 h = __floats2half2_rn(a, b);
    return *(uint32_t*)&h;
}

// ---------------------------------------------------------------------------
// fp32 -> fp16 convert (activations)
// ---------------------------------------------------------------------------
__global__ void cvt_fp16(const float4* __restrict__ src,
                         __half2* __restrict__ hi, int n4)
{
    int i = blockIdx.x * blockDim.x + threadIdx.x;
    if (i >= n4) return;
    float4 v = src[i];
    hi[2*i]   = __floats2half2_rn(v.x, v.y);
    hi[2*i+1] = __floats2half2_rn(v.z, v.w);
}

// ---------------------------------------------------------------------------
// transpose: W [K=1024][N] fp32 -> [N][K=1024] fp16
// ---------------------------------------------------------------------------
__global__ void tsplit_w(const float* __restrict__ src,
                         __half* __restrict__ hi, int N)
{
    __shared__ float t[32][33];
    const int n0 = blockIdx.x * 32, k0 = blockIdx.y * 32;
    const int tx = threadIdx.x, ty = threadIdx.y;
    #pragma unroll
    for (int r = ty; r < 32; r += 8)
        t[r][tx] = src[(size_t)(k0 + r) * N + n0 + tx];
    __syncthreads();
    #pragma unroll
    for (int r = ty; r < 32; r += 8)
        hi[(size_t)(n0 + r) * GK + k0 + tx] = __float2half(t[tx][r]);
}

// ---------------------------------------------------------------------------
// HMMA GEMM: C = A[M,1024] * B[N,1024]^T, pure fp16, fp32 accumulate.
// 128x128 tile, BK=32, 8 warps (2x4), cp.async double buffer, 2 CTA/SM.
// EPI=0: scatter into g_qhi (x0.125), g_khi, g_vhi    EPI=1: +bias -> Cout
// ---------------------------------------------------------------------------
#define BK 32
#define MATB (128 * 40 * 2)           // 10240 B per matrix tile (80B rows)
#define STAGEB (2 * MATB)             // 20480 (Ahi, Bhi)
#define GEMM_SMEM (2 * STAGEB)        // 40960

template<int EPI>
__global__ __launch_bounds__(256, 2)
void mma_gemm(const __half* __restrict__ Ahi, const __half* __restrict__ Bhi,
              const float* __restrict__ bias, float* __restrict__ Cout)
{
    extern __shared__ char smc[];
    const uint32_t sb = smem_u32(smc);

    const int tid = threadIdx.x;
    const int wid = tid >> 5, lane = tid & 31;
    const int warp_m = wid >> 2;      // 0..1
    const int warp_n = wid & 3;       // 0..3
    const int m0 = blockIdx.y * 128, n0 = blockIdx.x * 128;

    // async loader: 1024 16B chunks per stage, 4 per thread
    auto issue = [&](int kc, int s) {
        const uint32_t dstb = sb + s * STAGEB;
        #pragma unroll
        for (int i = 0; i < 4; i++) {
            int idx = i * 256 + tid;            // 0..1023
            int mtx = idx >> 9;                 // 0:Ahi 1:Bhi
            int r   = (idx >> 2) & 127;
            int c4  = idx & 3;
            const __half* p = (mtx == 0 ? Ahi + (size_t)(m0 + r) * GK
                                        : Bhi + (size_t)(n0 + r) * GK)
                              + kc * BK + c4 * 8;
            cp16(dstb + mtx * MATB + r * 80 + c4 * 16, p);
        }
        cp_commit();
    };

    float acc[4][4][4];
    #pragma unroll
    for (int a = 0; a < 4; a++)
        #pragma unroll
        for (int b = 0; b < 4; b++)
            #pragma unroll
            for (int c = 0; c < 4; c++) acc[a][b][c] = 0.f;

    issue(0, 0);
    const int NIT = GK / BK;            // 32
    for (int kc = 0; kc < NIT; kc++) {
        const int s = kc & 1;
        if (kc + 1 < NIT) { issue(kc + 1, s ^ 1); cp_wait<1>(); }
        else              { cp_wait<0>(); }
        __syncthreads();

        const uint32_t Ah = sb + s * STAGEB;
        const uint32_t Bh = Ah + MATB;

        #pragma unroll
        for (int ks = 0; ks < 2; ks++) {
            const uint32_t kb = ks * 32 + (lane >> 4) * 16;
            uint32_t ah[4][4];
            #pragma unroll
            for (int mt = 0; mt < 4; mt++) {
                uint32_t ro = (uint32_t)(warp_m * 64 + mt * 16 + (lane & 15)) * 80 + kb;
                ldsm4(ah[mt], Ah + ro);
            }
            const uint32_t kbb = ks * 32 + ((lane >> 3) & 1) * 16;
            #pragma unroll
            for (int nt = 0; nt < 4; nt++) {
                uint32_t ro = (uint32_t)(warp_n * 32 + nt * 8 + (lane & 7)) * 80 + kbb;
                uint32_t bh[2];
                ldsm2(bh, Bh + ro);
                #pragma unroll
                for (int mt = 0; mt < 4; mt++)
                    mma16816(acc[mt][nt], ah[mt], bh);
            }
        }
        __syncthreads();
    }

    const int g = lane >> 2, tg = lane & 3;
    #pragma unroll
    for (int mt = 0; mt < 4; mt++) {
        #pragma unroll
        for (int nt = 0; nt < 4; nt++) {
            const int c  = n0 + warp_n * 32 + nt * 8 + tg * 2;
            const int r0 = m0 + warp_m * 64 + mt * 16 + g;
            #pragma unroll
            for (int h = 0; h < 2; h++) {
                const int r = r0 + h * 8;
                float2 v = make_float2(acc[mt][nt][2*h], acc[mt][nt][2*h+1]);
                if (EPI == 0) {
                    const int bb = r >> 11, t = r & 2047;
                    const int mat = c >> 10, cc = c & 1023;
                    const int head = cc >> 6, d = cc & 63;
                    size_t o = (((size_t)(bb * HEADS + head) * TT + t) * HS + d) >> 1;
                    if (mat == 0) {
                        ((__half2*)g_qhi)[o] = __floats2half2_rn(v.x * 0.125f, v.y * 0.125f);
                    } else if (mat == 1) {
                        ((__half2*)g_khi)[o] = __floats2half2_rn(v.x, v.y);
                    } else {
                        ((__half2*)g_vhi)[o] = __floats2half2_rn(v.x, v.y);
                    }
                } else {
                    float2 bv = *(const float2*)(bias + c);
                    v.x += bv.x; v.y += bv.y;
                    *(float2*)(Cout + (size_t)r * EMB + c) = v;
                }
            }
        }
    }
}

// ---------------------------------------------------------------------------
// Tensor-core flash attention, pure fp16 operands, fp32 accumulate.
// BM=128, BN=64, hs=64, 8 warps; Q register-resident; K/V double-buffered.
// ---------------------------------------------------------------------------
#define ATILE_B  (64 * 144)            // 9216 B per 64-row tile
#define ASTAGE_B (2 * ATILE_B)         // Khi, Vhi = 18432
#define ATT_SMEM (2 * ASTAGE_B)        // 36864 (also covers Q staging: 18432)

__global__ __launch_bounds__(256)
void attn_mma()
{
    extern __shared__ char sm[];
    const uint32_t sb = smem_u32(sm);
    const int tid = threadIdx.x, wid = tid >> 5, lane = tid & 31;
    const int qt = gridDim.x - 1 - blockIdx.x;     // heavy tiles first
    const int bh = blockIdx.y;
    const int q0 = qt * 128;
    const int g = lane >> 2, tg = lane & 3;

    // ---- stage Q into smem, then ldmatrix to registers ----
    {
        const __half* Qh = g_qhi + ((size_t)bh * TT + q0) * HS;
        #pragma unroll
        for (int i = 0; i < 4; i++) {
            int idx = i * 256 + tid;               // 0..1023
            int r = idx >> 3, c8 = idx & 7;
            *(uint4*)(sm + r * 144 + c8 * 16) = *(const uint4*)(Qh + r * HS + c8 * 8);
        }
    }
    __syncthreads();
    uint32_t qh[4][4];
    #pragma unroll
    for (int kg = 0; kg < 4; kg++) {
        uint32_t a = sb + (uint32_t)(wid * 16 + (lane & 15)) * 144 + kg * 32 + (lane >> 4) * 16;
        ldsm4(qh[kg], a);
    }
    __syncthreads();

    // ---- K/V pipeline ----
    auto issueKV = [&](int kt, int s) {
        const uint32_t dstb = sb + s * ASTAGE_B;
        const size_t rowb = ((size_t)bh * TT + kt * 64) * HS;
        #pragma unroll
        for (int i = 0; i < 4; i++) {
            int idx = i * 256 + tid;               // 0..1023
            int mtx = idx >> 9;                    // 0 Khi 1 Vhi
            int r = (idx >> 3) & 63, c8 = idx & 7;
            const __half* p = (mtx == 0 ? g_khi : g_vhi) + rowb + r * HS + c8 * 8;
            cp16(dstb + mtx * ATILE_B + r * 144 + c8 * 16, p);
        }
        cp_commit();
    };

    float oacc[8][4];
    #pragma unroll
    for (int nt = 0; nt < 8; nt++)
        #pragma unroll
        for (int c = 0; c < 4; c++) oacc[nt][c] = 0.f;
    float mrow[2] = {-1e30f, -1e30f}, lrow[2] = {0.f, 0.f};

    const int dq = (q0 + wid * 16) >> 6;           // warp's diagonal 64-tile
    const int ktmax = 2 * qt + 1;

    issueKV(0, 0);
    for (int kt = 0; kt <= ktmax; kt++) {
        const int s = kt & 1;
        if (kt < ktmax) { issueKV(kt + 1, s ^ 1); cp_wait<1>(); }
        else            { cp_wait<0>(); }
        __syncthreads();

        if (kt <= dq) {
            const uint32_t base = sb + s * ASTAGE_B;

            // S = Q K^T
            float sacc[8][4];
            #pragma unroll
            for (int nt = 0; nt < 8; nt++)
                #pragma unroll
                for (int c = 0; c < 4; c++) sacc[nt][c] = 0.f;

            #pragma unroll
            for (int kg = 0; kg < 4; kg++) {
                #pragma unroll
                for (int nt = 0; nt < 8; nt++) {
                    uint32_t ro = base + (uint32_t)(nt * 8 + (lane & 7)) * 144
                                 + kg * 32 + ((lane >> 3) & 1) * 16;
                    uint32_t kbh[2];
                    ldsm2(kbh, ro);
                    mma16816(sacc[nt], qh[kg], kbh);
                }
            }

            // causal mask on the diagonal tile
            if (kt == dq) {
                const int rl = ((q0 + wid * 16) & 63) + g;
                #pragma unroll
                for (int nt = 0; nt < 8; nt++) {
                    int c0 = nt * 8 + tg * 2;
                    if (c0     > rl)     sacc[nt][0] = -1e30f;
                    if (c0 + 1 > rl)     sacc[nt][1] = -1e30f;
                    if (c0     > rl + 8) sacc[nt][2] = -1e30f;
                    if (c0 + 1 > rl + 8) sacc[nt][3] = -1e30f;
                }
            }

            // online softmax (rows g, g+8; quad reduction over tg)
            #pragma unroll
            for (int r = 0; r < 2; r++) {
                float mx = -1e30f;
                #pragma unroll
                for (int nt = 0; nt < 8; nt++)
                    mx = fmaxf(mx, fmaxf(sacc[nt][2*r], sacc[nt][2*r+1]));
                mx = fmaxf(mx, __shfl_xor_sync(0xffffffffu, mx, 1));
                mx = fmaxf(mx, __shfl_xor_sync(0xffffffffu, mx, 2));
                float mnew = fmaxf(mrow[r], mx);
                float corr = __expf(mrow[r] - mnew);
                float rs = 0.f;
                #pragma unroll
                for (int nt = 0; nt < 8; nt++) {
                    float p0 = __expf(sacc[nt][2*r]   - mnew);
                    float p1 = __expf(sacc[nt][2*r+1] - mnew);
                    sacc[nt][2*r] = p0; sacc[nt][2*r+1] = p1;
                    rs += p0 + p1;
                }
                rs += __shfl_xor_sync(0xffffffffu, rs, 1);
                rs += __shfl_xor_sync(0xffffffffu, rs, 2);
                lrow[r] = lrow[r] * corr + rs;
                mrow[r] = mnew;
                #pragma unroll
                for (int nt = 0; nt < 8; nt++) {
                    oacc[nt][2*r] *= corr; oacc[nt][2*r+1] *= corr;
                }
            }

            // O += P V  (P fp16 from S fragments; V via ldmatrix.trans)
            #pragma unroll
            for (int kg = 0; kg < 4; kg++) {
                uint32_t ph[4];
                #pragma unroll
                for (int q = 0; q < 4; q++) {
                    ph[q] = packh2(sacc[2*kg + (q >> 1)][(q & 1) * 2],
                                   sacc[2*kg + (q >> 1)][(q & 1) * 2 + 1]);
                }
                #pragma unroll
                for (int nt = 0; nt < 8; nt++) {
                    uint32_t ro = base + ATILE_B
                                 + (uint32_t)(kg * 16 + (lane & 15)) * 144 + nt * 16;
                    uint32_t vbh[2];
                    ldsm2t(vbh, ro);
                    mma16816(oacc[nt], ph, vbh);
                }
            }
        }
        __syncthreads();
    }

    // epilogue: write fp16 directly as the proj-GEMM A operand
    const int b = bh >> 4, h = bh & 15;
    #pragma unroll
    for (int r = 0; r < 2; r++) {
        float inv = 1.0f / lrow[r];
        int t = q0 + wid * 16 + g + r * 8;
        size_t rowo = ((size_t)(b * TT + t)) * EMB + h * HS;
        #pragma unroll
        for (int nt = 0; nt < 8; nt++) {
            size_t o = (rowo + nt * 8 + tg * 2) >> 1;
            ((__half2*)g_ahi)[o] =
                __floats2half2_rn(oacc[nt][2*r] * inv, oacc[nt][2*r+1] * inv);
        }
    }
}

// ---------------------------------------------------------------------------
extern "C" void kernel_launch(void* const* d_in, const int* in_sizes, int n_in,
                              void* d_out, int out_size)
{
    const float* x      = (const float*)d_in[0];
    const float* w_qkv  = (const float*)d_in[1];
    const float* w_proj = (const float*)d_in[2];
    const float* b_proj = (const float*)d_in[3];
    float* out = (float*)d_out;

    cudaFuncSetAttribute(attn_mma, cudaFuncAttributeMaxDynamicSharedMemorySize, ATT_SMEM);
    cudaFuncSetAttribute(mma_gemm<0>, cudaFuncAttributeMaxDynamicSharedMemorySize, GEMM_SMEM);
    cudaFuncSetAttribute(mma_gemm<1>, cudaFuncAttributeMaxDynamicSharedMemorySize, GEMM_SMEM);

    __half *xhi, *ahi, *wqhi, *wphi;
    cudaGetSymbolAddress((void**)&xhi,  g_xhi);
    cudaGetSymbolAddress((void**)&ahi,  g_ahi);
    cudaGetSymbolAddress((void**)&wqhi, g_wqhi);
    cudaGetSymbolAddress((void**)&wphi, g_wphi);

    // 1. convert x -> fp16
    cvt_fp16<<<(NROWS * GK / 4 + 255) / 256, 256>>>(
        (const float4*)x, (__half2*)xhi, NROWS * GK / 4);

    // 2. transpose weights to fp16
    tsplit_w<<<dim3(3 * EMB / 32, GK / 32), dim3(32, 8)>>>(w_qkv, wqhi, 3 * EMB);
    tsplit_w<<<dim3(EMB / 32, GK / 32), dim3(32, 8)>>>(w_proj, wphi, EMB);

    // 3. QKV GEMM (fp16) -> q (scaled), k, v
    mma_gemm<0><<<dim3(3 * EMB / 128, NROWS / 128), 256, GEMM_SMEM>>>(
        xhi, wqhi, nullptr, nullptr);

    // 4. tensor-core causal flash attention -> g_ahi
    attn_mma<<<dim3(TT / 128, BB * HEADS), 256, ATT_SMEM>>>();

    // 5. output projection (fp16) + bias
    mma_gemm<1><<<dim3(EMB / 128, NROWS / 128), 256, GEMM_SMEM>>>(
        ahi, wphi, b_proj, out);
}

// round 9
// speedup vs baseline: 2.7028x; 1.1288x over previous
#include <cuda_runtime.h>
#include <cuda_fp16.h>
#include <cstdint>
#include <math.h>

// Problem constants
#define BB 2
#define TT 2048
#define EMB 1024
#define HEADS 16
#define HS 64
#define NROWS (BB*TT)          // 4096
#define GK 1024                // K for both GEMMs

// ---------------------------------------------------------------------------
// Scratch (__device__ globals; allocation-free rule). 1-term fp16 everywhere.
// ---------------------------------------------------------------------------
__device__ __half g_qhi[(size_t)BB*HEADS*TT*HS];   // [bh][t][d], pre-scaled 0.125
__device__ __half g_khi[(size_t)BB*HEADS*TT*HS];
__device__ __half g_vhi[(size_t)BB*HEADS*TT*HS];

__device__ __half g_xhi[(size_t)NROWS*GK];
__device__ __half g_ahi[(size_t)NROWS*GK];         // attention out (proj input)
__device__ __half g_wqhi[(size_t)3*EMB*GK];        // [3072][1024] K-major
__device__ __half g_wphi[(size_t)EMB*GK];          // [1024][1024] K-major

// ---------------------------------------------------------------------------
// PTX helpers (portable sm_80+ subset: ldmatrix / mma.sync / cp.async)
// ---------------------------------------------------------------------------
__device__ __forceinline__ uint32_t smem_u32(const void* p) {
    uint32_t a;
    asm("{ .reg .u64 t; cvta.to.shared.u64 t, %1; cvt.u32.u64 %0, t; }" : "=r"(a) : "l"(p));
    return a;
}
__device__ __forceinline__ void cp16(uint32_t dst, const void* src) {
    asm volatile("cp.async.cg.shared.global [%0], [%1], 16;" :: "r"(dst), "l"(src));
}
__device__ __forceinline__ void cp_commit() {
    asm volatile("cp.async.commit_group;" ::: "memory");
}
template<int N>
__device__ __forceinline__ void cp_wait() {
    asm volatile("cp.async.wait_group %0;" :: "n"(N) : "memory");
}
__device__ __forceinline__ void ldsm4(uint32_t* r, uint32_t a) {
    asm volatile("ldmatrix.sync.aligned.m8n8.x4.shared.b16 {%0,%1,%2,%3}, [%4];"
        : "=r"(r[0]), "=r"(r[1]), "=r"(r[2]), "=r"(r[3]) : "r"(a));
}
// trans x4: four 8x8 col-major-delivered matrices (V pairing)
__device__ __forceinline__ void ldsm4t(uint32_t* r, uint32_t a) {
    asm volatile("ldmatrix.sync.aligned.m8n8.x4.trans.shared.b16 {%0,%1,%2,%3}, [%4];"
        : "=r"(r[0]), "=r"(r[1]), "=r"(r[2]), "=r"(r[3]) : "r"(a));
}
__device__ __forceinline__ void mma16816(float* d, const uint32_t* a, const uint32_t* b) {
    asm volatile("mma.sync.aligned.m16n8k16.row.col.f32.f16.f16.f32 "
        "{%0,%1,%2,%3}, {%4,%5,%6,%7}, {%8,%9}, {%0,%1,%2,%3};"
        : "+f"(d[0]), "+f"(d[1]), "+f"(d[2]), "+f"(d[3])
        : "r"(a[0]), "r"(a[1]), "r"(a[2]), "r"(a[3]), "r"(b[0]), "r"(b[1]));
}
__device__ __forceinline__ uint32_t packh2(float a, float b) {
    __half2 h = __floats2half2_rn(a, b);
    return *(uint32_t*)&h;
}

// ---------------------------------------------------------------------------
// fp32 -> fp16 convert (activations)
// ---------------------------------------------------------------------------
__global__ void cvt_fp16(const float4* __restrict__ src,
                         __half2* __restrict__ hi, int n4)
{
    int i = blockIdx.x * blockDim.x + threadIdx.x;
    if (i >= n4) return;
    float4 v = src[i];
    hi[2*i]   = __floats2half2_rn(v.x, v.y);
    hi[2*i+1] = __floats2half2_rn(v.z, v.w);
}

// ---------------------------------------------------------------------------
// transpose: W [K=1024][N] fp32 -> [N][K=1024] fp16
// ---------------------------------------------------------------------------
__global__ void tsplit_w(const float* __restrict__ src,
                         __half* __restrict__ hi, int N)
{
    __shared__ float t[32][33];
    const int n0 = blockIdx.x * 32, k0 = blockIdx.y * 32;
    const int tx = threadIdx.x, ty = threadIdx.y;
    #pragma unroll
    for (int r = ty; r < 32; r += 8)
        t[r][tx] = src[(size_t)(k0 + r) * N + n0 + tx];
    __syncthreads();
    #pragma unroll
    for (int r = ty; r < 32; r += 8)
        hi[(size_t)(n0 + r) * GK + k0 + tx] = __float2half(t[tx][r]);
}

// ---------------------------------------------------------------------------
// HMMA GEMM: C = A[M,1024] * B[N,1024]^T, pure fp16, fp32 accumulate.
// 128x128 tile, BK=64 (16 iters), 8 warps (2x4), double buffer, 2 CTA/SM.
// 144B row stride (conflict-free ldmatrix). B-frags via paired ldsm4.
// EPI=0: scatter into g_qhi (x0.125), g_khi, g_vhi    EPI=1: +bias -> Cout
// ---------------------------------------------------------------------------
#define BKG 64
#define MATB2 (128 * 144)             // 18432 B per matrix tile
#define STAGEB (2 * MATB2)            // 36864 (Ahi, Bhi)
#define GEMM_SMEM (2 * STAGEB)        // 73728

template<int EPI>
__global__ __launch_bounds__(256, 2)
void mma_gemm(const __half* __restrict__ Ahi, const __half* __restrict__ Bhi,
              const float* __restrict__ bias, float* __restrict__ Cout)
{
    extern __shared__ char smc[];
    const uint32_t sb = smem_u32(smc);

    const int tid = threadIdx.x;
    const int wid = tid >> 5, lane = tid & 31;
    const int warp_m = wid >> 2;      // 0..1
    const int warp_n = wid & 3;       // 0..3
    const int m0 = blockIdx.y * 128, n0 = blockIdx.x * 128;

    // async loader: 2048 16B chunks per stage (A,B tiles), 8 per thread
    auto issue = [&](int kc, int s) {
        const uint32_t dstb = sb + s * STAGEB;
        #pragma unroll
        for (int i = 0; i < 8; i++) {
            int idx = i * 256 + tid;            // 0..2047
            int mtx = idx >> 10;                // 0:Ahi 1:Bhi
            int r   = (idx >> 3) & 127;
            int c8  = idx & 7;
            const __half* p = (mtx == 0 ? Ahi + (size_t)(m0 + r) * GK
                                        : Bhi + (size_t)(n0 + r) * GK)
                              + kc * BKG + c8 * 8;
            cp16(dstb + mtx * MATB2 + r * 144 + c8 * 16, p);
        }
        cp_commit();
    };

    float acc[4][4][4];
    #pragma unroll
    for (int a = 0; a < 4; a++)
        #pragma unroll
        for (int b = 0; b < 4; b++)
            #pragma unroll
            for (int c = 0; c < 4; c++) acc[a][b][c] = 0.f;

    issue(0, 0);
    const int NIT = GK / BKG;           // 16
    for (int kc = 0; kc < NIT; kc++) {
        const int s = kc & 1;
        if (kc + 1 < NIT) { issue(kc + 1, s ^ 1); cp_wait<1>(); }
        else              { cp_wait<0>(); }
        __syncthreads();

        const uint32_t Ah = sb + s * STAGEB;
        const uint32_t Bh = Ah + MATB2;

        #pragma unroll
        for (int ks = 0; ks < 4; ks++) {
            const uint32_t kb = ks * 32 + (lane >> 4) * 16;
            uint32_t ah[4][4];
            #pragma unroll
            for (int mt = 0; mt < 4; mt++) {
                uint32_t ro = Ah + (uint32_t)(warp_m * 64 + mt * 16 + (lane & 15)) * 144 + kb;
                ldsm4(ah[mt], ro);
            }
            const uint32_t kbb = ks * 32 + ((lane >> 3) & 1) * 16;
            #pragma unroll
            for (int ntp = 0; ntp < 2; ntp++) {
                // paired B: m0,m1 -> nt=2ntp (k0-7,k8-15); m2,m3 -> nt=2ntp+1
                uint32_t ro = Bh + (uint32_t)(warp_n * 32 + ntp * 16
                             + (lane >> 4) * 8 + (lane & 7)) * 144 + kbb;
                uint32_t bb[4];
                ldsm4(bb, ro);
                #pragma unroll
                for (int mt = 0; mt < 4; mt++) {
                    mma16816(acc[mt][2*ntp],     ah[mt], bb);
                    mma16816(acc[mt][2*ntp + 1], ah[mt], bb + 2);
                }
            }
        }
        __syncthreads();
    }

    const int g = lane >> 2, tg = lane & 3;
    #pragma unroll
    for (int mt = 0; mt < 4; mt++) {
        #pragma unroll
        for (int nt = 0; nt < 4; nt++) {
            const int c  = n0 + warp_n * 32 + nt * 8 + tg * 2;
            const int r0 = m0 + warp_m * 64 + mt * 16 + g;
            #pragma unroll
            for (int h = 0; h < 2; h++) {
                const int r = r0 + h * 8;
                float2 v = make_float2(acc[mt][nt][2*h], acc[mt][nt][2*h+1]);
                if (EPI == 0) {
                    const int bb2 = r >> 11, t = r & 2047;
                    const int mat = c >> 10, cc = c & 1023;
                    const int head = cc >> 6, d = cc & 63;
                    size_t o = (((size_t)(bb2 * HEADS + head) * TT + t) * HS + d) >> 1;
                    if (mat == 0) {
                        ((__half2*)g_qhi)[o] = __floats2half2_rn(v.x * 0.125f, v.y * 0.125f);
                    } else if (mat == 1) {
                        ((__half2*)g_khi)[o] = __floats2half2_rn(v.x, v.y);
                    } else {
                        ((__half2*)g_vhi)[o] = __floats2half2_rn(v.x, v.y);
                    }
                } else {
                    float2 bv = *(const float2*)(bias + c);
                    v.x += bv.x; v.y += bv.y;
                    *(float2*)(Cout + (size_t)r * EMB + c) = v;
                }
            }
        }
    }
}

// ---------------------------------------------------------------------------
// Tensor-core flash attention, pure fp16 operands, fp32 accumulate.
// BM=128, BN=64, hs=64, 8 warps; Q register-resident.
// 4 K/V buffers, 2 tiles consumed per barrier pair; paired ldsm4/ldsm4t.
// ---------------------------------------------------------------------------
#define ATILE_B  (64 * 144)            // 9216 B per 64-row tile
#define ASTAGE_B (2 * ATILE_B)         // Khi, Vhi = 18432
#define ATT_SMEM (4 * ASTAGE_B)        // 73728 (4 buffers; covers Q staging)

__global__ __launch_bounds__(256)
void attn_mma()
{
    extern __shared__ char sm[];
    const uint32_t sb = smem_u32(sm);
    const int tid = threadIdx.x, wid = tid >> 5, lane = tid & 31;
    const int qt = gridDim.x - 1 - blockIdx.x;     // heavy tiles first
    const int bh = blockIdx.y;
    const int q0 = qt * 128;
    const int g = lane >> 2, tg = lane & 3;

    // ---- stage Q into smem, then ldmatrix to registers ----
    {
        const __half* Qh = g_qhi + ((size_t)bh * TT + q0) * HS;
        #pragma unroll
        for (int i = 0; i < 4; i++) {
            int idx = i * 256 + tid;               // 0..1023
            int r = idx >> 3, c8 = idx & 7;
            *(uint4*)(sm + r * 144 + c8 * 16) = *(const uint4*)(Qh + r * HS + c8 * 8);
        }
    }
    __syncthreads();
    uint32_t qh[4][4];
    #pragma unroll
    for (int kg = 0; kg < 4; kg++) {
        uint32_t a = sb + (uint32_t)(wid * 16 + (lane & 15)) * 144 + kg * 32 + (lane >> 4) * 16;
        ldsm4(qh[kg], a);
    }
    __syncthreads();

    // ---- K/V pipeline: buffer = tile & 3 ----
    auto issueKV = [&](int kt) {
        const uint32_t dstb = sb + (kt & 3) * ASTAGE_B;
        const size_t rowb = ((size_t)bh * TT + kt * 64) * HS;
        #pragma unroll
        for (int i = 0; i < 4; i++) {
            int idx = i * 256 + tid;               // 0..1023
            int mtx = idx >> 9;                    // 0 Khi 1 Vhi
            int r = (idx >> 3) & 63, c8 = idx & 7;
            const __half* p = (mtx == 0 ? g_khi : g_vhi) + rowb + r * HS + c8 * 8;
            cp16(dstb + mtx * ATILE_B + r * 144 + c8 * 16, p);
        }
        cp_commit();
    };

    float oacc[8][4];
    #pragma unroll
    for (int nt = 0; nt < 8; nt++)
        #pragma unroll
        for (int c = 0; c < 4; c++) oacc[nt][c] = 0.f;
    float mrow[2] = {-1e30f, -1e30f}, lrow[2] = {0.f, 0.f};

    const int dq = (q0 + wid * 16) >> 6;           // warp's diagonal 64-tile
    const int NT = 2 * qt + 2;                     // always even

    issueKV(0); issueKV(1);
    if (NT > 2) { issueKV(2); issueKV(3); }

    for (int j = 0; j < NT / 2; j++) {
        if (2 * j + 3 >= NT) cp_wait<0>(); else cp_wait<2>();
        __syncthreads();

        #pragma unroll
        for (int tt = 0; tt < 2; tt++) {
            const int kt = 2 * j + tt;
            if (kt > dq) continue;
            const uint32_t base = sb + (kt & 3) * ASTAGE_B;

            // S = Q K^T  (paired ldsm4 for K)
            float sacc[8][4];
            #pragma unroll
            for (int nt = 0; nt < 8; nt++)
                #pragma unroll
                for (int c = 0; c < 4; c++) sacc[nt][c] = 0.f;

            #pragma unroll
            for (int kg = 0; kg < 4; kg++) {
                const uint32_t kbb = kg * 32 + ((lane >> 3) & 1) * 16;
                #pragma unroll
                for (int ntp = 0; ntp < 4; ntp++) {
                    uint32_t ro = base + (uint32_t)(ntp * 16
                                 + (lane >> 4) * 8 + (lane & 7)) * 144 + kbb;
                    uint32_t kb4[4];
                    ldsm4(kb4, ro);
                    mma16816(sacc[2*ntp],     qh[kg], kb4);
                    mma16816(sacc[2*ntp + 1], qh[kg], kb4 + 2);
                }
            }

            // causal mask on the diagonal tile
            if (kt == dq) {
                const int rl = ((q0 + wid * 16) & 63) + g;
                #pragma unroll
                for (int nt = 0; nt < 8; nt++) {
                    int c0 = nt * 8 + tg * 2;
                    if (c0     > rl)     sacc[nt][0] = -1e30f;
                    if (c0 + 1 > rl)     sacc[nt][1] = -1e30f;
                    if (c0     > rl + 8) sacc[nt][2] = -1e30f;
                    if (c0 + 1 > rl + 8) sacc[nt][3] = -1e30f;
                }
            }

            // online softmax (rows g, g+8; quad reduction over tg)
            #pragma unroll
            for (int r = 0; r < 2; r++) {
                float mx = -1e30f;
                #pragma unroll
                for (int nt = 0; nt < 8; nt++)
                    mx = fmaxf(mx, fmaxf(sacc[nt][2*r], sacc[nt][2*r+1]));
                mx = fmaxf(mx, __shfl_xor_sync(0xffffffffu, mx, 1));
                mx = fmaxf(mx, __shfl_xor_sync(0xffffffffu, mx, 2));
                float mnew = fmaxf(mrow[r], mx);
                float corr = __expf(mrow[r] - mnew);
                float rs = 0.f;
                #pragma unroll
                for (int nt = 0; nt < 8; nt++) {
                    float p0 = __expf(sacc[nt][2*r]   - mnew);
                    float p1 = __expf(sacc[nt][2*r+1] - mnew);
                    sacc[nt][2*r] = p0; sacc[nt][2*r+1] = p1;
                    rs += p0 + p1;
                }
                rs += __shfl_xor_sync(0xffffffffu, rs, 1);
                rs += __shfl_xor_sync(0xffffffffu, rs, 2);
                lrow[r] = lrow[r] * corr + rs;
                mrow[r] = mnew;
                #pragma unroll
                for (int nt = 0; nt < 8; nt++) {
                    oacc[nt][2*r] *= corr; oacc[nt][2*r+1] *= corr;
                }
            }

            // O += P V  (paired ldsm4t for V)
            #pragma unroll
            for (int kg = 0; kg < 4; kg++) {
                uint32_t ph[4];
                #pragma unroll
                for (int q = 0; q < 4; q++) {
                    ph[q] = packh2(sacc[2*kg + (q >> 1)][(q & 1) * 2],
                                   sacc[2*kg + (q >> 1)][(q & 1) * 2 + 1]);
                }
                #pragma unroll
                for (int ntp = 0; ntp < 4; ntp++) {
                    uint32_t ro = base + ATILE_B
                                 + (uint32_t)(kg * 16 + (lane & 15)) * 144
                                 + ntp * 32 + (lane >> 4) * 16;
                    uint32_t vb4[4];
                    ldsm4t(vb4, ro);
                    mma16816(oacc[2*ntp],     ph, vb4);
                    mma16816(oacc[2*ntp + 1], ph, vb4 + 2);
                }
            }
        }
        __syncthreads();
        if (2 * j + 4 < NT) issueKV(2 * j + 4);
        if (2 * j + 5 < NT) issueKV(2 * j + 5);
    }

    // epilogue: write fp16 directly as the proj-GEMM A operand
    const int b = bh >> 4, h = bh & 15;
    #pragma unroll
    for (int r = 0; r < 2; r++) {
        float inv = 1.0f / lrow[r];
        int t = q0 + wid * 16 + g + r * 8;
        size_t rowo = ((size_t)(b * TT + t)) * EMB + h * HS;
        #pragma unroll
        for (int nt = 0; nt < 8; nt++) {
            size_t o = (rowo + nt * 8 + tg * 2) >> 1;
            ((__half2*)g_ahi)[o] =
                __floats2half2_rn(oacc[nt][2*r] * inv, oacc[nt][2*r+1] * inv);
        }
    }
}

// ---------------------------------------------------------------------------
extern "C" void kernel_launch(void* const* d_in, const int* in_sizes, int n_in,
                              void* d_out, int out_size)
{
    const float* x      = (const float*)d_in[0];
    const float* w_qkv  = (const float*)d_in[1];
    const float* w_proj = (const float*)d_in[2];
    const float* b_proj = (const float*)d_in[3];
    float* out = (float*)d_out;

    cudaFuncSetAttribute(attn_mma, cudaFuncAttributeMaxDynamicSharedMemorySize, ATT_SMEM);
    cudaFuncSetAttribute(mma_gemm<0>, cudaFuncAttributeMaxDynamicSharedMemorySize, GEMM_SMEM);
    cudaFuncSetAttribute(mma_gemm<1>, cudaFuncAttributeMaxDynamicSharedMemorySize, GEMM_SMEM);

    __half *xhi, *ahi, *wqhi, *wphi;
    cudaGetSymbolAddress((void**)&xhi,  g_xhi);
    cudaGetSymbolAddress((void**)&ahi,  g_ahi);
    cudaGetSymbolAddress((void**)&wqhi, g_wqhi);
    cudaGetSymbolAddress((void**)&wphi, g_wphi);

    // 1. convert x -> fp16
    cvt_fp16<<<(NROWS * GK / 4 + 255) / 256, 256>>>(
        (const float4*)x, (__half2*)xhi, NROWS * GK / 4);

    // 2. transpose weights to fp16
    tsplit_w<<<dim3(3 * EMB / 32, GK / 32), dim3(32, 8)>>>(w_qkv, wqhi, 3 * EMB);
    tsplit_w<<<dim3(EMB / 32, GK / 32), dim3(32, 8)>>>(w_proj, wphi, EMB);

    // 3. QKV GEMM (fp16, BK=64) -> q (scaled), k, v
    mma_gemm<0><<<dim3(3 * EMB / 128, NROWS / 128), 256, GEMM_SMEM>>>(
        xhi, wqhi, nullptr, nullptr);

    // 4. tensor-core causal flash attention -> g_ahi
    attn_mma<<<dim3(TT / 128, BB * HEADS), 256, ATT_SMEM>>>();

    // 5. output projection (fp16, BK=64) + bias
    mma_gemm<1><<<dim3(EMB / 128, NROWS / 128), 256, GEMM_SMEM>>>(
        ahi, wphi, b_proj, out);
}

// round 10
// speedup vs baseline: 2.8199x; 1.0433x over previous
#include <cuda_runtime.h>
#include <cuda_fp16.h>
#include <cstdint>
#include <math.h>

// Problem constants
#define BB 2
#define TT 2048
#define EMB 1024
#define HEADS 16
#define HS 64
#define NROWS (BB*TT)          // 4096
#define GK 1024                // K for both GEMMs

// Q pre-scale: hs^-0.5 * log2(e)  (softmax runs in exp2 domain)
#define QSCALE 0.180336880f

// ---------------------------------------------------------------------------
// Scratch (__device__ globals; allocation-free rule). 1-term fp16 everywhere.
// ---------------------------------------------------------------------------
__device__ __half g_qhi[(size_t)BB*HEADS*TT*HS];   // [bh][t][d], pre-scaled QSCALE
__device__ __half g_khi[(size_t)BB*HEADS*TT*HS];
__device__ __half g_vhi[(size_t)BB*HEADS*TT*HS];

__device__ __half g_xhi[(size_t)NROWS*GK];
__device__ __half g_ahi[(size_t)NROWS*GK];         // attention out (proj input)
__device__ __half g_wqhi[(size_t)3*EMB*GK];        // [3072][1024] K-major
__device__ __half g_wphi[(size_t)EMB*GK];          // [1024][1024] K-major

// ---------------------------------------------------------------------------
// PTX helpers (portable sm_80+ subset: ldmatrix / mma.sync / cp.async)
// ---------------------------------------------------------------------------
__device__ __forceinline__ uint32_t smem_u32(const void* p) {
    uint32_t a;
    asm("{ .reg .u64 t; cvta.to.shared.u64 t, %1; cvt.u32.u64 %0, t; }" : "=r"(a) : "l"(p));
    return a;
}
__device__ __forceinline__ void cp16(uint32_t dst, const void* src) {
    asm volatile("cp.async.cg.shared.global [%0], [%1], 16;" :: "r"(dst), "l"(src));
}
__device__ __forceinline__ void cp_commit() {
    asm volatile("cp.async.commit_group;" ::: "memory");
}
template<int N>
__device__ __forceinline__ void cp_wait() {
    asm volatile("cp.async.wait_group %0;" :: "n"(N) : "memory");
}
__device__ __forceinline__ void ldsm4(uint32_t* r, uint32_t a) {
    asm volatile("ldmatrix.sync.aligned.m8n8.x4.shared.b16 {%0,%1,%2,%3}, [%4];"
        : "=r"(r[0]), "=r"(r[1]), "=r"(r[2]), "=r"(r[3]) : "r"(a));
}
// trans x4: four 8x8 col-major-delivered matrices (V pairing)
__device__ __forceinline__ void ldsm4t(uint32_t* r, uint32_t a) {
    asm volatile("ldmatrix.sync.aligned.m8n8.x4.trans.shared.b16 {%0,%1,%2,%3}, [%4];"
        : "=r"(r[0]), "=r"(r[1]), "=r"(r[2]), "=r"(r[3]) : "r"(a));
}
__device__ __forceinline__ void mma16816(float* d, const uint32_t* a, const uint32_t* b) {
    asm volatile("mma.sync.aligned.m16n8k16.row.col.f32.f16.f16.f32 "
        "{%0,%1,%2,%3}, {%4,%5,%6,%7}, {%8,%9}, {%0,%1,%2,%3};"
        : "+f"(d[0]), "+f"(d[1]), "+f"(d[2]), "+f"(d[3])
        : "r"(a[0]), "r"(a[1]), "r"(a[2]), "r"(a[3]), "r"(b[0]), "r"(b[1]));
}
__device__ __forceinline__ uint32_t packh2(float a, float b) {
    __half2 h = __floats2half2_rn(a, b);
    return *(uint32_t*)&h;
}

// ---------------------------------------------------------------------------
// Merged prep kernel (single launch):
//  seg0 [0,4096):        cvt x fp32 -> fp16            (4096 blocks)
//  seg1 [4096,7168):     transpose w_qkv -> [N][K]     (3072 blocks)
//  seg2 [7168,8192):     transpose w_proj -> [N][K]    (1024 blocks)
// 256 threads/block throughout.
// ---------------------------------------------------------------------------
__global__ void prep_all(const float4* __restrict__ x, __half2* __restrict__ xhi,
                         const float* __restrict__ wq, __half* __restrict__ wqhi,
                         const float* __restrict__ wp, __half* __restrict__ wphi)
{
    __shared__ float t[32][33];
    const int b = blockIdx.x;
    const int tid = threadIdx.x;

    if (b < 4096) {
        int i = b * 256 + tid;               // float4 index, n4 = 1048576
        float4 v = x[i];
        xhi[2*i]   = __floats2half2_rn(v.x, v.y);
        xhi[2*i+1] = __floats2half2_rn(v.z, v.w);
        return;
    }

    const float* src;  __half* dst;  int N, bb;
    if (b < 7168) { bb = b - 4096; src = wq; dst = wqhi; N = 3 * EMB; }
    else          { bb = b - 7168; src = wp; dst = wphi; N = EMB; }

    const int nblk = N / 32;
    const int n0 = (bb % nblk) * 32, k0 = (bb / nblk) * 32;
    const int tx = tid & 31, ty = tid >> 5;

    #pragma unroll
    for (int r = ty; r < 32; r += 8)
        t[r][tx] = src[(size_t)(k0 + r) * N + n0 + tx];
    __syncthreads();
    #pragma unroll
    for (int r = ty; r < 32; r += 8)
        dst[(size_t)(n0 + r) * GK + k0 + tx] = __float2half(t[tx][r]);
}

// ---------------------------------------------------------------------------
// HMMA GEMM: C = A[M,1024] * B[N,1024]^T, pure fp16, fp32 accumulate.
// 128x128 tile, BK=64 (16 iters), 8 warps (2x4), double buffer, 2 CTA/SM.
// 144B row stride (conflict-free ldmatrix). B-frags via paired ldsm4.
// EPI=0: scatter into g_qhi (xQSCALE), g_khi, g_vhi    EPI=1: +bias -> Cout
// ---------------------------------------------------------------------------
#define BKG 64
#define MATB2 (128 * 144)             // 18432 B per matrix tile
#define STAGEB (2 * MATB2)            // 36864 (Ahi, Bhi)
#define GEMM_SMEM (2 * STAGEB)        // 73728

template<int EPI>
__global__ __launch_bounds__(256, 2)
void mma_gemm(const __half* __restrict__ Ahi, const __half* __restrict__ Bhi,
              const float* __restrict__ bias, float* __restrict__ Cout)
{
    extern __shared__ char smc[];
    const uint32_t sb = smem_u32(smc);

    const int tid = threadIdx.x;
    const int wid = tid >> 5, lane = tid & 31;
    const int warp_m = wid >> 2;      // 0..1
    const int warp_n = wid & 3;       // 0..3
    const int m0 = blockIdx.y * 128, n0 = blockIdx.x * 128;

    // async loader: 2048 16B chunks per stage (A,B tiles), 8 per thread
    auto issue = [&](int kc, int s) {
        const uint32_t dstb = sb + s * STAGEB;
        #pragma unroll
        for (int i = 0; i < 8; i++) {
            int idx = i * 256 + tid;            // 0..2047
            int mtx = idx >> 10;                // 0:Ahi 1:Bhi
            int r   = (idx >> 3) & 127;
            int c8  = idx & 7;
            const __half* p = (mtx == 0 ? Ahi + (size_t)(m0 + r) * GK
                                        : Bhi + (size_t)(n0 + r) * GK)
                              + kc * BKG + c8 * 8;
            cp16(dstb + mtx * MATB2 + r * 144 + c8 * 16, p);
        }
        cp_commit();
    };

    float acc[4][4][4];
    #pragma unroll
    for (int a = 0; a < 4; a++)
        #pragma unroll
        for (int b = 0; b < 4; b++)
            #pragma unroll
            for (int c = 0; c < 4; c++) acc[a][b][c] = 0.f;

    issue(0, 0);
    const int NIT = GK / BKG;           // 16
    for (int kc = 0; kc < NIT; kc++) {
        const int s = kc & 1;
        if (kc + 1 < NIT) { issue(kc + 1, s ^ 1); cp_wait<1>(); }
        else              { cp_wait<0>(); }
        __syncthreads();

        const uint32_t Ah = sb + s * STAGEB;
        const uint32_t Bh = Ah + MATB2;

        #pragma unroll
        for (int ks = 0; ks < 4; ks++) {
            const uint32_t kb = ks * 32 + (lane >> 4) * 16;
            uint32_t ah[4][4];
            #pragma unroll
            for (int mt = 0; mt < 4; mt++) {
                uint32_t ro = Ah + (uint32_t)(warp_m * 64 + mt * 16 + (lane & 15)) * 144 + kb;
                ldsm4(ah[mt], ro);
            }
            const uint32_t kbb = ks * 32 + ((lane >> 3) & 1) * 16;
            #pragma unroll
            for (int ntp = 0; ntp < 2; ntp++) {
                uint32_t ro = Bh + (uint32_t)(warp_n * 32 + ntp * 16
                             + (lane >> 4) * 8 + (lane & 7)) * 144 + kbb;
                uint32_t bb[4];
                ldsm4(bb, ro);
                #pragma unroll
                for (int mt = 0; mt < 4; mt++) {
                    mma16816(acc[mt][2*ntp],     ah[mt], bb);
                    mma16816(acc[mt][2*ntp + 1], ah[mt], bb + 2);
                }
            }
        }
        __syncthreads();
    }

    const int g = lane >> 2, tg = lane & 3;
    #pragma unroll
    for (int mt = 0; mt < 4; mt++) {
        #pragma unroll
        for (int nt = 0; nt < 4; nt++) {
            const int c  = n0 + warp_n * 32 + nt * 8 + tg * 2;
            const int r0 = m0 + warp_m * 64 + mt * 16 + g;
            #pragma unroll
            for (int h = 0; h < 2; h++) {
                const int r = r0 + h * 8;
                float2 v = make_float2(acc[mt][nt][2*h], acc[mt][nt][2*h+1]);
                if (EPI == 0) {
                    const int bb2 = r >> 11, t = r & 2047;
                    const int mat = c >> 10, cc = c & 1023;
                    const int head = cc >> 6, d = cc & 63;
                    size_t o = (((size_t)(bb2 * HEADS + head) * TT + t) * HS + d) >> 1;
                    if (mat == 0) {
                        ((__half2*)g_qhi)[o] = __floats2half2_rn(v.x * QSCALE, v.y * QSCALE);
                    } else if (mat == 1) {
                        ((__half2*)g_khi)[o] = __floats2half2_rn(v.x, v.y);
                    } else {
                        ((__half2*)g_vhi)[o] = __floats2half2_rn(v.x, v.y);
                    }
                } else {
                    float2 bv = *(const float2*)(bias + c);
                    v.x += bv.x; v.y += bv.y;
                    *(float2*)(Cout + (size_t)r * EMB + c) = v;
                }
            }
        }
    }
}

// ---------------------------------------------------------------------------
// Tensor-core flash attention, pure fp16 operands, fp32 accumulate.
// Softmax in exp2 domain (log2e folded into Q). BM=128, BN=64, 8 warps.
// 4 K/V buffers, 2 tiles consumed per barrier pair; paired ldsm4/ldsm4t.
// ---------------------------------------------------------------------------
#define ATILE_B  (64 * 144)            // 9216 B per 64-row tile
#define ASTAGE_B (2 * ATILE_B)         // Khi, Vhi = 18432
#define ATT_SMEM (4 * ASTAGE_B)        // 73728 (4 buffers; covers Q staging)

__global__ __launch_bounds__(256, 2)
void attn_mma()
{
    extern __shared__ char sm[];
    const uint32_t sb = smem_u32(sm);
    const int tid = threadIdx.x, wid = tid >> 5, lane = tid & 31;
    const int qt = gridDim.x - 1 - blockIdx.x;     // heavy tiles first
    const int bh = blockIdx.y;
    const int q0 = qt * 128;
    const int g = lane >> 2, tg = lane & 3;

    // ---- stage Q into smem, then ldmatrix to registers ----
    {
        const __half* Qh = g_qhi + ((size_t)bh * TT + q0) * HS;
        #pragma unroll
        for (int i = 0; i < 4; i++) {
            int idx = i * 256 + tid;               // 0..1023
            int r = idx >> 3, c8 = idx & 7;
            *(uint4*)(sm + r * 144 + c8 * 16) = *(const uint4*)(Qh + r * HS + c8 * 8);
        }
    }
    __syncthreads();
    uint32_t qh[4][4];
    #pragma unroll
    for (int kg = 0; kg < 4; kg++) {
        uint32_t a = sb + (uint32_t)(wid * 16 + (lane & 15)) * 144 + kg * 32 + (lane >> 4) * 16;
        ldsm4(qh[kg], a);
    }
    __syncthreads();

    // ---- K/V pipeline: buffer = tile & 3 ----
    auto issueKV = [&](int kt) {
        const uint32_t dstb = sb + (kt & 3) * ASTAGE_B;
        const size_t rowb = ((size_t)bh * TT + kt * 64) * HS;
        #pragma unroll
        for (int i = 0; i < 4; i++) {
            int idx = i * 256 + tid;               // 0..1023
            int mtx = idx >> 9;                    // 0 Khi 1 Vhi
            int r = (idx >> 3) & 63, c8 = idx & 7;
            const __half* p = (mtx == 0 ? g_khi : g_vhi) + rowb + r * HS + c8 * 8;
            cp16(dstb + mtx * ATILE_B + r * 144 + c8 * 16, p);
        }
        cp_commit();
    };

    float oacc[8][4];
    #pragma unroll
    for (int nt = 0; nt < 8; nt++)
        #pragma unroll
        for (int c = 0; c < 4; c++) oacc[nt][c] = 0.f;
    float mrow[2] = {-1e30f, -1e30f}, lrow[2] = {0.f, 0.f};

    const int dq = (q0 + wid * 16) >> 6;           // warp's diagonal 64-tile
    const int NT = 2 * qt + 2;                     // always even

    issueKV(0); issueKV(1);
    if (NT > 2) { issueKV(2); issueKV(3); }

    for (int j = 0; j < NT / 2; j++) {
        if (2 * j + 3 >= NT) cp_wait<0>(); else cp_wait<2>();
        __syncthreads();

        #pragma unroll
        for (int tt = 0; tt < 2; tt++) {
            const int kt = 2 * j + tt;
            if (kt > dq) continue;
            const uint32_t base = sb + (kt & 3) * ASTAGE_B;

            // S = Q K^T  (paired ldsm4 for K)   [exp2 domain]
            float sacc[8][4];
            #pragma unroll
            for (int nt = 0; nt < 8; nt++)
                #pragma unroll
                for (int c = 0; c < 4; c++) sacc[nt][c] = 0.f;

            #pragma unroll
            for (int kg = 0; kg < 4; kg++) {
                const uint32_t kbb = kg * 32 + ((lane >> 3) & 1) * 16;
                #pragma unroll
                for (int ntp = 0; ntp < 4; ntp++) {
                    uint32_t ro = base + (uint32_t)(ntp * 16
                                 + (lane >> 4) * 8 + (lane & 7)) * 144 + kbb;
                    uint32_t kb4[4];
                    ldsm4(kb4, ro);
                    mma16816(sacc[2*ntp],     qh[kg], kb4);
                    mma16816(sacc[2*ntp + 1], qh[kg], kb4 + 2);
                }
            }

            // causal mask on the diagonal tile
            if (kt == dq) {
                const int rl = ((q0 + wid * 16) & 63) + g;
                #pragma unroll
                for (int nt = 0; nt < 8; nt++) {
                    int c0 = nt * 8 + tg * 2;
                    if (c0     > rl)     sacc[nt][0] = -1e30f;
                    if (c0 + 1 > rl)     sacc[nt][1] = -1e30f;
                    if (c0     > rl + 8) sacc[nt][2] = -1e30f;
                    if (c0 + 1 > rl + 8) sacc[nt][3] = -1e30f;
                }
            }

            // online softmax in exp2 domain (rows g, g+8; quad reduction)
            #pragma unroll
            for (int r = 0; r < 2; r++) {
                float mx = -1e30f;
                #pragma unroll
                for (int nt = 0; nt < 8; nt++)
                    mx = fmaxf(mx, fmaxf(sacc[nt][2*r], sacc[nt][2*r+1]));
                mx = fmaxf(mx, __shfl_xor_sync(0xffffffffu, mx, 1));
                mx = fmaxf(mx, __shfl_xor_sync(0xffffffffu, mx, 2));
                float mnew = fmaxf(mrow[r], mx);
                float corr = exp2f(mrow[r] - mnew);
                float rs = 0.f;
                #pragma unroll
                for (int nt = 0; nt < 8; nt++) {
                    float p0 = exp2f(sacc[nt][2*r]   - mnew);
                    float p1 = exp2f(sacc[nt][2*r+1] - mnew);
                    sacc[nt][2*r] = p0; sacc[nt][2*r+1] = p1;
                    rs += p0 + p1;
                }
                rs += __shfl_xor_sync(0xffffffffu, rs, 1);
                rs += __shfl_xor_sync(0xffffffffu, rs, 2);
                lrow[r] = lrow[r] * corr + rs;
                mrow[r] = mnew;
                #pragma unroll
                for (int nt = 0; nt < 8; nt++) {
                    oacc[nt][2*r] *= corr; oacc[nt][2*r+1] *= corr;
                }
            }

            // O += P V  (paired ldsm4t for V)
            #pragma unroll
            for (int kg = 0; kg < 4; kg++) {
                uint32_t ph[4];
                #pragma unroll
                for (int q = 0; q < 4; q++) {
                    ph[q] = packh2(sacc[2*kg + (q >> 1)][(q & 1) * 2],
                                   sacc[2*kg + (q >> 1)][(q & 1) * 2 + 1]);
                }
                #pragma unroll
                for (int ntp = 0; ntp < 4; ntp++) {
                    uint32_t ro = base + ATILE_B
                                 + (uint32_t)(kg * 16 + (lane & 15)) * 144
                                 + ntp * 32 + (lane >> 4) * 16;
                    uint32_t vb4[4];
                    ldsm4t(vb4, ro);
                    mma16816(oacc[2*ntp],     ph, vb4);
                    mma16816(oacc[2*ntp + 1], ph, vb4 + 2);
                }
            }
        }
        __syncthreads();
        if (2 * j + 4 < NT) issueKV(2 * j + 4);
        if (2 * j + 5 < NT) issueKV(2 * j + 5);
    }

    // epilogue: write fp16 directly as the proj-GEMM A operand
    const int b = bh >> 4, h = bh & 15;
    #pragma unroll
    for (int r = 0; r < 2; r++) {
        float inv = 1.0f / lrow[r];
        int t = q0 + wid * 16 + g + r * 8;
        size_t rowo = ((size_t)(b * TT + t)) * EMB + h * HS;
        #pragma unroll
        for (int nt = 0; nt < 8; nt++) {
            size_t o = (rowo + nt * 8 + tg * 2) >> 1;
            ((__half2*)g_ahi)[o] =
                __floats2half2_rn(oacc[nt][2*r] * inv, oacc[nt][2*r+1] * inv);
        }
    }
}

// ---------------------------------------------------------------------------
extern "C" void kernel_launch(void* const* d_in, const int* in_sizes, int n_in,
                              void* d_out, int out_size)
{
    const float* x      = (const float*)d_in[0];
    const float* w_qkv  = (const float*)d_in[1];
    const float* w_proj = (const float*)d_in[2];
    const float* b_proj = (const float*)d_in[3];
    float* out = (float*)d_out;

    cudaFuncSetAttribute(attn_mma, cudaFuncAttributeMaxDynamicSharedMemorySize, ATT_SMEM);
    cudaFuncSetAttribute(mma_gemm<0>, cudaFuncAttributeMaxDynamicSharedMemorySize, GEMM_SMEM);
    cudaFuncSetAttribute(mma_gemm<1>, cudaFuncAttributeMaxDynamicSharedMemorySize, GEMM_SMEM);

    __half *xhi, *ahi, *wqhi, *wphi;
    cudaGetSymbolAddress((void**)&xhi,  g_xhi);
    cudaGetSymbolAddress((void**)&ahi,  g_ahi);
    cudaGetSymbolAddress((void**)&wqhi, g_wqhi);
    cudaGetSymbolAddress((void**)&wphi, g_wphi);

    // 1. merged prep: cvt x + transpose both weight matrices (one launch)
    prep_all<<<8192, 256>>>((const float4*)x, (__half2*)xhi,
                            w_qkv, wqhi, w_proj, wphi);

    // 2. QKV GEMM (fp16, BK=64) -> q (xQSCALE), k, v
    mma_gemm<0><<<dim3(3 * EMB / 128, NROWS / 128), 256, GEMM_SMEM>>>(
        xhi, wqhi, nullptr, nullptr);

    // 3. tensor-core causal flash attention (exp2 softmax) -> g_ahi
    attn_mma<<<dim3(TT / 128, BB * HEADS), 256, ATT_SMEM>>>();

    // 4. output projection (fp16, BK=64) + bias
    mma_gemm<1><<<dim3(EMB / 128, NROWS / 128), 256, GEMM_SMEM>>>(
        ahi, wphi, b_proj, out);
}

// round 11
// speedup vs baseline: 3.1282x; 1.1094x over previous
#include <cuda_runtime.h>
#include <cuda_fp16.h>
#include <cstdint>
#include <math.h>

// Problem constants
#define BB 2
#define TT 2048
#define EMB 1024
#define HEADS 16
#define HS 64
#define NROWS (BB*TT)          // 4096
#define GK 1024                // K for both GEMMs

// Q pre-scale: hs^-0.5 * log2(e)  (softmax runs in exp2 domain)
#define QSCALE 0.180336880f

// ---------------------------------------------------------------------------
// Scratch (__device__ globals; allocation-free rule). 1-term fp16 everywhere.
// ---------------------------------------------------------------------------
__device__ __half g_qhi[(size_t)BB*HEADS*TT*HS];   // [bh][t][d], pre-scaled QSCALE
__device__ __half g_khi[(size_t)BB*HEADS*TT*HS];
__device__ __half g_vhi[(size_t)BB*HEADS*TT*HS];

__device__ __half g_xhi[(size_t)NROWS*GK];
__device__ __half g_ahi[(size_t)NROWS*GK];         // attention out (proj input)
__device__ __half g_wqhi[(size_t)3*EMB*GK];        // [3072][1024] K-major
__device__ __half g_wphi[(size_t)EMB*GK];          // [1024][1024] K-major

// ---------------------------------------------------------------------------
// PTX helpers (portable sm_80+ subset: ldmatrix / mma.sync / cp.async)
// ---------------------------------------------------------------------------
__device__ __forceinline__ uint32_t smem_u32(const void* p) {
    uint32_t a;
    asm("{ .reg .u64 t; cvta.to.shared.u64 t, %1; cvt.u32.u64 %0, t; }" : "=r"(a) : "l"(p));
    return a;
}
__device__ __forceinline__ void cp16(uint32_t dst, const void* src) {
    asm volatile("cp.async.cg.shared.global [%0], [%1], 16;" :: "r"(dst), "l"(src));
}
__device__ __forceinline__ void cp_commit() {
    asm volatile("cp.async.commit_group;" ::: "memory");
}
template<int N>
__device__ __forceinline__ void cp_wait() {
    asm volatile("cp.async.wait_group %0;" :: "n"(N) : "memory");
}
__device__ __forceinline__ void ldsm4(uint32_t* r, uint32_t a) {
    asm volatile("ldmatrix.sync.aligned.m8n8.x4.shared.b16 {%0,%1,%2,%3}, [%4];"
        : "=r"(r[0]), "=r"(r[1]), "=r"(r[2]), "=r"(r[3]) : "r"(a));
}
// trans x4: four 8x8 col-major-delivered matrices (V pairing)
__device__ __forceinline__ void ldsm4t(uint32_t* r, uint32_t a) {
    asm volatile("ldmatrix.sync.aligned.m8n8.x4.trans.shared.b16 {%0,%1,%2,%3}, [%4];"
        : "=r"(r[0]), "=r"(r[1]), "=r"(r[2]), "=r"(r[3]) : "r"(a));
}
__device__ __forceinline__ void mma16816(float* d, const uint32_t* a, const uint32_t* b) {
    asm volatile("mma.sync.aligned.m16n8k16.row.col.f32.f16.f16.f32 "
        "{%0,%1,%2,%3}, {%4,%5,%6,%7}, {%8,%9}, {%0,%1,%2,%3};"
        : "+f"(d[0]), "+f"(d[1]), "+f"(d[2]), "+f"(d[3])
        : "r"(a[0]), "r"(a[1]), "r"(a[2]), "r"(a[3]), "r"(b[0]), "r"(b[1]));
}
__device__ __forceinline__ uint32_t packh2(float a, float b) {
    __half2 h = __floats2half2_rn(a, b);
    return *(uint32_t*)&h;
}

// ---------------------------------------------------------------------------
// Merged prep kernel (single launch):
//  seg0 [0,4096):        cvt x fp32 -> fp16            (4096 blocks)
//  seg1 [4096,7168):     transpose w_qkv -> [N][K]     (3072 blocks)
//  seg2 [7168,8192):     transpose w_proj -> [N][K]    (1024 blocks)
// ---------------------------------------------------------------------------
__global__ void prep_all(const float4* __restrict__ x, __half2* __restrict__ xhi,
                         const float* __restrict__ wq, __half* __restrict__ wqhi,
                         const float* __restrict__ wp, __half* __restrict__ wphi)
{
    __shared__ float t[32][33];
    const int b = blockIdx.x;
    const int tid = threadIdx.x;

    if (b < 4096) {
        int i = b * 256 + tid;               // float4 index, n4 = 1048576
        float4 v = x[i];
        xhi[2*i]   = __floats2half2_rn(v.x, v.y);
        xhi[2*i+1] = __floats2half2_rn(v.z, v.w);
        return;
    }

    const float* src;  __half* dst;  int N, bb;
    if (b < 7168) { bb = b - 4096; src = wq; dst = wqhi; N = 3 * EMB; }
    else          { bb = b - 7168; src = wp; dst = wphi; N = EMB; }

    const int nblk = N / 32;
    const int n0 = (bb % nblk) * 32, k0 = (bb / nblk) * 32;
    const int tx = tid & 31, ty = tid >> 5;

    #pragma unroll
    for (int r = ty; r < 32; r += 8)
        t[r][tx] = src[(size_t)(k0 + r) * N + n0 + tx];
    __syncthreads();
    #pragma unroll
    for (int r = ty; r < 32; r += 8)
        dst[(size_t)(n0 + r) * GK + k0 + tx] = __float2half(t[tx][r]);
}

// ---------------------------------------------------------------------------
// HMMA GEMM (R9/R10-validated, frozen): C = A[M,1024] * B[N,1024]^T, fp16.
// 128x128 tile, BK=64 (16 iters), 8 warps (2x4), double buffer, 2 CTA/SM.
// EPI=0: scatter into g_qhi (xQSCALE), g_khi, g_vhi    EPI=1: +bias -> Cout
// ---------------------------------------------------------------------------
#define BKG 64
#define MATB2 (128 * 144)             // 18432 B per matrix tile
#define STAGEB (2 * MATB2)            // 36864 (Ahi, Bhi)
#define GEMM_SMEM (2 * STAGEB)        // 73728

template<int EPI>
__global__ __launch_bounds__(256, 2)
void mma_gemm(const __half* __restrict__ Ahi, const __half* __restrict__ Bhi,
              const float* __restrict__ bias, float* __restrict__ Cout)
{
    extern __shared__ char smc[];
    const uint32_t sb = smem_u32(smc);

    const int tid = threadIdx.x;
    const int wid = tid >> 5, lane = tid & 31;
    const int warp_m = wid >> 2;      // 0..1
    const int warp_n = wid & 3;       // 0..3
    const int m0 = blockIdx.y * 128, n0 = blockIdx.x * 128;

    auto issue = [&](int kc, int s) {
        const uint32_t dstb = sb + s * STAGEB;
        #pragma unroll
        for (int i = 0; i < 8; i++) {
            int idx = i * 256 + tid;            // 0..2047
            int mtx = idx >> 10;                // 0:Ahi 1:Bhi
            int r   = (idx >> 3) & 127;
            int c8  = idx & 7;
            const __half* p = (mtx == 0 ? Ahi + (size_t)(m0 + r) * GK
                                        : Bhi + (size_t)(n0 + r) * GK)
                              + kc * BKG + c8 * 8;
            cp16(dstb + mtx * MATB2 + r * 144 + c8 * 16, p);
        }
        cp_commit();
    };

    float acc[4][4][4];
    #pragma unroll
    for (int a = 0; a < 4; a++)
        #pragma unroll
        for (int b = 0; b < 4; b++)
            #pragma unroll
            for (int c = 0; c < 4; c++) acc[a][b][c] = 0.f;

    issue(0, 0);
    const int NIT = GK / BKG;           // 16
    for (int kc = 0; kc < NIT; kc++) {
        const int s = kc & 1;
        if (kc + 1 < NIT) { issue(kc + 1, s ^ 1); cp_wait<1>(); }
        else              { cp_wait<0>(); }
        __syncthreads();

        const uint32_t Ah = sb + s * STAGEB;
        const uint32_t Bh = Ah + MATB2;

        #pragma unroll
        for (int ks = 0; ks < 4; ks++) {
            const uint32_t kb = ks * 32 + (lane >> 4) * 16;
            uint32_t ah[4][4];
            #pragma unroll
            for (int mt = 0; mt < 4; mt++) {
                uint32_t ro = Ah + (uint32_t)(warp_m * 64 + mt * 16 + (lane & 15)) * 144 + kb;
                ldsm4(ah[mt], ro);
            }
            const uint32_t kbb = ks * 32 + ((lane >> 3) & 1) * 16;
            #pragma unroll
            for (int ntp = 0; ntp < 2; ntp++) {
                uint32_t ro = Bh + (uint32_t)(warp_n * 32 + ntp * 16
                             + (lane >> 4) * 8 + (lane & 7)) * 144 + kbb;
                uint32_t bb[4];
                ldsm4(bb, ro);
                #pragma unroll
                for (int mt = 0; mt < 4; mt++) {
                    mma16816(acc[mt][2*ntp],     ah[mt], bb);
                    mma16816(acc[mt][2*ntp + 1], ah[mt], bb + 2);
                }
            }
        }
        __syncthreads();
    }

    const int g = lane >> 2, tg = lane & 3;
    #pragma unroll
    for (int mt = 0; mt < 4; mt++) {
        #pragma unroll
        for (int nt = 0; nt < 4; nt++) {
            const int c  = n0 + warp_n * 32 + nt * 8 + tg * 2;
            const int r0 = m0 + warp_m * 64 + mt * 16 + g;
            #pragma unroll
            for (int h = 0; h < 2; h++) {
                const int r = r0 + h * 8;
                float2 v = make_float2(acc[mt][nt][2*h], acc[mt][nt][2*h+1]);
                if (EPI == 0) {
                    const int bb2 = r >> 11, t = r & 2047;
                    const int mat = c >> 10, cc = c & 1023;
                    const int head = cc >> 6, d = cc & 63;
                    size_t o = (((size_t)(bb2 * HEADS + head) * TT + t) * HS + d) >> 1;
                    if (mat == 0) {
                        ((__half2*)g_qhi)[o] = __floats2half2_rn(v.x * QSCALE, v.y * QSCALE);
                    } else if (mat == 1) {
                        ((__half2*)g_khi)[o] = __floats2half2_rn(v.x, v.y);
                    } else {
                        ((__half2*)g_vhi)[o] = __floats2half2_rn(v.x, v.y);
                    }
                } else {
                    float2 bv = *(const float2*)(bias + c);
                    v.x += bv.x; v.y += bv.y;
                    *(float2*)(Cout + (size_t)r * EMB + c) = v;
                }
            }
        }
    }
}

// ---------------------------------------------------------------------------
// Tensor-core flash attention, fp16, exp2-domain softmax. BM=128, BN=64.
// Grid (bh, qtile) with qtile heavy-first => global LPT scheduling.
// Odd warps process the 2-tile window in reverse order => de-phased softmax
// keeps the tensor pipe fed while other warps run softmax.
// ---------------------------------------------------------------------------
#define ATILE_B  (64 * 144)            // 9216 B per 64-row tile
#define ASTAGE_B (2 * ATILE_B)         // Khi, Vhi = 18432
#define ATT_SMEM (4 * ASTAGE_B)        // 73728 (4 buffers; covers Q staging)

__global__ __launch_bounds__(256, 2)
void attn_mma()
{
    extern __shared__ char sm[];
    const uint32_t sb = smem_u32(sm);
    const int tid = threadIdx.x, wid = tid >> 5, lane = tid & 31;
    const int bh = blockIdx.x;                     // 0..31
    const int qt = gridDim.y - 1 - blockIdx.y;     // heavy tiles first, globally
    const int q0 = qt * 128;
    const int g = lane >> 2, tg = lane & 3;

    // ---- stage Q into smem, then ldmatrix to registers ----
    {
        const __half* Qh = g_qhi + ((size_t)bh * TT + q0) * HS;
        #pragma unroll
        for (int i = 0; i < 4; i++) {
            int idx = i * 256 + tid;               // 0..1023
            int r = idx >> 3, c8 = idx & 7;
            *(uint4*)(sm + r * 144 + c8 * 16) = *(const uint4*)(Qh + r * HS + c8 * 8);
        }
    }
    __syncthreads();
    uint32_t qh[4][4];
    #pragma unroll
    for (int kg = 0; kg < 4; kg++) {
        uint32_t a = sb + (uint32_t)(wid * 16 + (lane & 15)) * 144 + kg * 32 + (lane >> 4) * 16;
        ldsm4(qh[kg], a);
    }
    __syncthreads();

    // ---- K/V pipeline: buffer = tile & 3 ----
    auto issueKV = [&](int kt) {
        const uint32_t dstb = sb + (kt & 3) * ASTAGE_B;
        const size_t rowb = ((size_t)bh * TT + kt * 64) * HS;
        #pragma unroll
        for (int i = 0; i < 4; i++) {
            int idx = i * 256 + tid;               // 0..1023
            int mtx = idx >> 9;                    // 0 Khi 1 Vhi
            int r = (idx >> 3) & 63, c8 = idx & 7;
            const __half* p = (mtx == 0 ? g_khi : g_vhi) + rowb + r * HS + c8 * 8;
            cp16(dstb + mtx * ATILE_B + r * 144 + c8 * 16, p);
        }
        cp_commit();
    };

    float oacc[8][4];
    #pragma unroll
    for (int nt = 0; nt < 8; nt++)
        #pragma unroll
        for (int c = 0; c < 4; c++) oacc[nt][c] = 0.f;
    float mrow[2] = {-1e30f, -1e30f}, lrow[2] = {0.f, 0.f};

    const int dq = (q0 + wid * 16) >> 6;           // warp's diagonal 64-tile
    const int NT = 2 * qt + 2;                     // always even
    const int first = wid & 1;                     // de-phase: odd warps reverse

    issueKV(0); issueKV(1);
    if (NT > 2) { issueKV(2); issueKV(3); }

    for (int j = 0; j < NT / 2; j++) {
        if (2 * j + 3 >= NT) cp_wait<0>(); else cp_wait<2>();
        __syncthreads();

        #pragma unroll
        for (int u = 0; u < 2; u++) {
            const int tt = first ^ u;
            const int kt = 2 * j + tt;
            if (kt > dq) continue;
            const uint32_t base = sb + (kt & 3) * ASTAGE_B;

            // S = Q K^T  (paired ldsm4 for K)   [exp2 domain]
            float sacc[8][4];
            #pragma unroll
            for (int nt = 0; nt < 8; nt++)
                #pragma unroll
                for (int c = 0; c < 4; c++) sacc[nt][c] = 0.f;

            #pragma unroll
            for (int kg = 0; kg < 4; kg++) {
                const uint32_t kbb = kg * 32 + ((lane >> 3) & 1) * 16;
                #pragma unroll
                for (int ntp = 0; ntp < 4; ntp++) {
                    uint32_t ro = base + (uint32_t)(ntp * 16
                                 + (lane >> 4) * 8 + (lane & 7)) * 144 + kbb;
                    uint32_t kb4[4];
                    ldsm4(kb4, ro);
                    mma16816(sacc[2*ntp],     qh[kg], kb4);
                    mma16816(sacc[2*ntp + 1], qh[kg], kb4 + 2);
                }
            }

            // causal mask on the diagonal tile
            if (kt == dq) {
                const int rl = ((q0 + wid * 16) & 63) + g;
                #pragma unroll
                for (int nt = 0; nt < 8; nt++) {
                    int c0 = nt * 8 + tg * 2;
                    if (c0     > rl)     sacc[nt][0] = -1e30f;
                    if (c0 + 1 > rl)     sacc[nt][1] = -1e30f;
                    if (c0     > rl + 8) sacc[nt][2] = -1e30f;
                    if (c0 + 1 > rl + 8) sacc[nt][3] = -1e30f;
                }
            }

            // online softmax in exp2 domain (rows g, g+8; quad reduction)
            #pragma unroll
            for (int r = 0; r < 2; r++) {
                float mx = -1e30f;
                #pragma unroll
                for (int nt = 0; nt < 8; nt++)
                    mx = fmaxf(mx, fmaxf(sacc[nt][2*r], sacc[nt][2*r+1]));
                mx = fmaxf(mx, __shfl_xor_sync(0xffffffffu, mx, 1));
                mx = fmaxf(mx, __shfl_xor_sync(0xffffffffu, mx, 2));
                float mnew = fmaxf(mrow[r], mx);
                float corr = exp2f(mrow[r] - mnew);
                float rs = 0.f;
                #pragma unroll
                for (int nt = 0; nt < 8; nt++) {
                    float p0 = exp2f(sacc[nt][2*r]   - mnew);
                    float p1 = exp2f(sacc[nt][2*r+1] - mnew);
                    sacc[nt][2*r] = p0; sacc[nt][2*r+1] = p1;
                    rs += p0 + p1;
                }
                rs += __shfl_xor_sync(0xffffffffu, rs, 1);
                rs += __shfl_xor_sync(0xffffffffu, rs, 2);
                lrow[r] = lrow[r] * corr + rs;
                mrow[r] = mnew;
                #pragma unroll
                for (int nt = 0; nt < 8; nt++) {
                    oacc[nt][2*r] *= corr; oacc[nt][2*r+1] *= corr;
                }
            }

            // O += P V  (paired ldsm4t for V)
            #pragma unroll
            for (int kg = 0; kg < 4; kg++) {
                uint32_t ph[4];
                #pragma unroll
                for (int q = 0; q < 4; q++) {
                    ph[q] = packh2(sacc[2*kg + (q >> 1)][(q & 1) * 2],
                                   sacc[2*kg + (q >> 1)][(q & 1) * 2 + 1]);
                }
                #pragma unroll
                for (int ntp = 0; ntp < 4; ntp++) {
                    uint32_t ro = base + ATILE_B
                                 + (uint32_t)(kg * 16 + (lane & 15)) * 144
                                 + ntp * 32 + (lane >> 4) * 16;
                    uint32_t vb4[4];
                    ldsm4t(vb4, ro);
                    mma16816(oacc[2*ntp],     ph, vb4);
                    mma16816(oacc[2*ntp + 1], ph, vb4 + 2);
                }
            }
        }
        __syncthreads();
        if (2 * j + 4 < NT) issueKV(2 * j + 4);
        if (2 * j + 5 < NT) issueKV(2 * j + 5);
    }

    // epilogue: write fp16 directly as the proj-GEMM A operand
    const int b = bh >> 4, h = bh & 15;
    #pragma unroll
    for (int r = 0; r < 2; r++) {
        float inv = 1.0f / lrow[r];
        int t = q0 + wid * 16 + g + r * 8;
        size_t rowo = ((size_t)(b * TT + t)) * EMB + h * HS;
        #pragma unroll
        for (int nt = 0; nt < 8; nt++) {
            size_t o = (rowo + nt * 8 + tg * 2) >> 1;
            ((__half2*)g_ahi)[o] =
                __floats2half2_rn(oacc[nt][2*r] * inv, oacc[nt][2*r+1] * inv);
        }
    }
}

// ---------------------------------------------------------------------------
extern "C" void kernel_launch(void* const* d_in, const int* in_sizes, int n_in,
                              void* d_out, int out_size)
{
    const float* x      = (const float*)d_in[0];
    const float* w_qkv  = (const float*)d_in[1];
    const float* w_proj = (const float*)d_in[2];
    const float* b_proj = (const float*)d_in[3];
    float* out = (float*)d_out;

    cudaFuncSetAttribute(attn_mma, cudaFuncAttributeMaxDynamicSharedMemorySize, ATT_SMEM);
    cudaFuncSetAttribute(mma_gemm<0>, cudaFuncAttributeMaxDynamicSharedMemorySize, GEMM_SMEM);
    cudaFuncSetAttribute(mma_gemm<1>, cudaFuncAttributeMaxDynamicSharedMemorySize, GEMM_SMEM);

    __half *xhi, *ahi, *wqhi, *wphi;
    cudaGetSymbolAddress((void**)&xhi,  g_xhi);
    cudaGetSymbolAddress((void**)&ahi,  g_ahi);
    cudaGetSymbolAddress((void**)&wqhi, g_wqhi);
    cudaGetSymbolAddress((void**)&wphi, g_wphi);

    // 1. merged prep: cvt x + transpose both weight matrices (one launch)
    prep_all<<<8192, 256>>>((const float4*)x, (__half2*)xhi,
                            w_qkv, wqhi, w_proj, wphi);

    // 2. QKV GEMM (fp16, BK=64) -> q (xQSCALE), k, v
    mma_gemm<0><<<dim3(3 * EMB / 128, NROWS / 128), 256, GEMM_SMEM>>>(
        xhi, wqhi, nullptr, nullptr);

    // 3. tensor-core causal flash attention (LPT grid, de-phased warps)
    attn_mma<<<dim3(BB * HEADS, TT / 128), 256, ATT_SMEM>>>();

    // 4. output projection (fp16, BK=64) + bias
    mma_gemm<1><<<dim3(EMB / 128, NROWS / 128), 256, GEMM_SMEM>>>(
        ahi, wphi, b_proj, out);
}

// round 12
// speedup vs baseline: 3.1491x; 1.0067x over previous
#include <cuda_runtime.h>
#include <cuda_fp16.h>
#include <cstdint>
#include <math.h>

// Problem constants
#define BB 2
#define TT 2048
#define EMB 1024
#define HEADS 16
#define HS 64
#define NROWS (BB*TT)          // 4096
#define GK 1024                // K for both GEMMs

// Q pre-scale: hs^-0.5 * log2(e)  (softmax runs in exp2 domain)
#define QSCALE 0.180336880f

// ---------------------------------------------------------------------------
// Scratch (__device__ globals; allocation-free rule). 1-term fp16 everywhere.
// Weights stay in native [K][N] layout (no transpose) — B frags via ldsm4t.
// ---------------------------------------------------------------------------
__device__ __half g_qhi[(size_t)BB*HEADS*TT*HS];   // [bh][t][d], pre-scaled QSCALE
__device__ __half g_khi[(size_t)BB*HEADS*TT*HS];
__device__ __half g_vhi[(size_t)BB*HEADS*TT*HS];

__device__ __half g_xhi[(size_t)NROWS*GK];
__device__ __half g_ahi[(size_t)NROWS*GK];         // attention out (proj input)
__device__ __half g_wqhi[(size_t)GK*3*EMB];        // [1024][3072] K-major rows
__device__ __half g_wphi[(size_t)GK*EMB];          // [1024][1024] K-major rows

// ---------------------------------------------------------------------------
// PTX helpers (portable sm_80+ subset: ldmatrix / mma.sync / cp.async)
// ---------------------------------------------------------------------------
__device__ __forceinline__ uint32_t smem_u32(const void* p) {
    uint32_t a;
    asm("{ .reg .u64 t; cvta.to.shared.u64 t, %1; cvt.u32.u64 %0, t; }" : "=r"(a) : "l"(p));
    return a;
}
__device__ __forceinline__ void cp16(uint32_t dst, const void* src) {
    asm volatile("cp.async.cg.shared.global [%0], [%1], 16;" :: "r"(dst), "l"(src));
}
__device__ __forceinline__ void cp_commit() {
    asm volatile("cp.async.commit_group;" ::: "memory");
}
template<int N>
__device__ __forceinline__ void cp_wait() {
    asm volatile("cp.async.wait_group %0;" :: "n"(N) : "memory");
}
__device__ __forceinline__ void ldsm4(uint32_t* r, uint32_t a) {
    asm volatile("ldmatrix.sync.aligned.m8n8.x4.shared.b16 {%0,%1,%2,%3}, [%4];"
        : "=r"(r[0]), "=r"(r[1]), "=r"(r[2]), "=r"(r[3]) : "r"(a));
}
// trans x4: [k][n]-stored rows -> col-major B fragments (validated on V path)
__device__ __forceinline__ void ldsm4t(uint32_t* r, uint32_t a) {
    asm volatile("ldmatrix.sync.aligned.m8n8.x4.trans.shared.b16 {%0,%1,%2,%3}, [%4];"
        : "=r"(r[0]), "=r"(r[1]), "=r"(r[2]), "=r"(r[3]) : "r"(a));
}
__device__ __forceinline__ void mma16816(float* d, const uint32_t* a, const uint32_t* b) {
    asm volatile("mma.sync.aligned.m16n8k16.row.col.f32.f16.f16.f32 "
        "{%0,%1,%2,%3}, {%4,%5,%6,%7}, {%8,%9}, {%0,%1,%2,%3};"
        : "+f"(d[0]), "+f"(d[1]), "+f"(d[2]), "+f"(d[3])
        : "r"(a[0]), "r"(a[1]), "r"(a[2]), "r"(a[3]), "r"(b[0]), "r"(b[1]));
}
__device__ __forceinline__ uint32_t packh2(float a, float b) {
    __half2 h = __floats2half2_rn(a, b);
    return *(uint32_t*)&h;
}

// ---------------------------------------------------------------------------
// Prep: pure elementwise fp32 -> fp16 convert of x, w_qkv, w_proj (flat).
//  x:  1,048,576 float4   wq: 786,432 float4   wp: 262,144 float4
//  total 2,097,152 float4 / 256 threads = 8192 blocks
// ---------------------------------------------------------------------------
#define NX4  1048576
#define NWQ4 786432

__global__ void prep_all(const float4* __restrict__ x, __half2* __restrict__ xo,
                         const float4* __restrict__ wq, __half2* __restrict__ wqo,
                         const float4* __restrict__ wp, __half2* __restrict__ wpo)
{
    int i = blockIdx.x * 256 + threadIdx.x;
    const float4* src; __half2* dst;
    if (i < NX4)             { src = x;  dst = xo; }
    else if (i < NX4 + NWQ4) { src = wq; dst = wqo; i -= NX4; }
    else                     { src = wp; dst = wpo; i -= NX4 + NWQ4; }
    float4 v = src[i];
    dst[2*i]   = __floats2half2_rn(v.x, v.y);
    dst[2*i+1] = __floats2half2_rn(v.z, v.w);
}

// ---------------------------------------------------------------------------
// HMMA GEMM: C[M,N] = A[M,1024] * W[1024,N], fp16, fp32 accumulate.
// A [M][K] K-major (144B rows, ldsm4); W [K][N] native (272B rows, ldsm4t).
// 128x128 tile, BK=64 (16 iters), 8 warps (2x4), double buffer, 2 CTA/SM.
// EPI=0: scatter into g_qhi (xQSCALE), g_khi, g_vhi    EPI=1: +bias -> Cout
// ---------------------------------------------------------------------------
#define BKG 64
#define MATA (128 * 144)              // 18432 B A tile
#define MATW (64 * 272)               // 17408 B W tile (64 k-rows x 256B+16pad)
#define STAGEB (MATA + MATW)          // 35840
#define GEMM_SMEM (2 * STAGEB)        // 71680

template<int EPI>
__global__ __launch_bounds__(256, 2)
void mma_gemm(const __half* __restrict__ Ahi, const __half* __restrict__ Wm,
              const float* __restrict__ bias, float* __restrict__ Cout, int Nw)
{
    extern __shared__ char smc[];
    const uint32_t sb = smem_u32(smc);

    const int tid = threadIdx.x;
    const int wid = tid >> 5, lane = tid & 31;
    const int warp_m = wid >> 2;      // 0..1
    const int warp_n = wid & 3;       // 0..3
    const int m0 = blockIdx.y * 128, n0 = blockIdx.x * 128;

    // async loader: A = 1024 chunks, W = 1024 chunks per stage; 8 per thread
    auto issue = [&](int kc, int s) {
        const uint32_t dstb = sb + s * STAGEB;
        #pragma unroll
        for (int i = 0; i < 8; i++) {
            int idx = i * 256 + tid;            // 0..2047
            if (idx < 1024) {                   // A tile: 128 rows x 8 chunks
                int r = idx >> 3, c8 = idx & 7;
                cp16(dstb + r * 144 + c8 * 16,
                     Ahi + (size_t)(m0 + r) * GK + kc * BKG + c8 * 8);
            } else {                            // W tile: 64 k-rows x 16 chunks
                int i2 = idx - 1024;
                int r = i2 >> 4, c16 = i2 & 15;
                cp16(dstb + MATA + r * 272 + c16 * 16,
                     Wm + (size_t)(kc * BKG + r) * Nw + n0 + c16 * 8);
            }
        }
        cp_commit();
    };

    float acc[4][4][4];
    #pragma unroll
    for (int a = 0; a < 4; a++)
        #pragma unroll
        for (int b = 0; b < 4; b++)
            #pragma unroll
            for (int c = 0; c < 4; c++) acc[a][b][c] = 0.f;

    issue(0, 0);
    const int NIT = GK / BKG;           // 16
    for (int kc = 0; kc < NIT; kc++) {
        const int s = kc & 1;
        if (kc + 1 < NIT) { issue(kc + 1, s ^ 1); cp_wait<1>(); }
        else              { cp_wait<0>(); }
        __syncthreads();

        const uint32_t Ah = sb + s * STAGEB;
        const uint32_t Wh = Ah + MATA;

        #pragma unroll
        for (int ks = 0; ks < 4; ks++) {
            const uint32_t kb = ks * 32 + (lane >> 4) * 16;
            uint32_t ah[4][4];
            #pragma unroll
            for (int mt = 0; mt < 4; mt++) {
                uint32_t ro = Ah + (uint32_t)(warp_m * 64 + mt * 16 + (lane & 15)) * 144 + kb;
                ldsm4(ah[mt], ro);
            }
            // W fragments: k-rows ks*16.., warp's 32 n-cols, via trans ldmatrix
            #pragma unroll
            for (int ntp = 0; ntp < 2; ntp++) {
                uint32_t ro = Wh + (uint32_t)(ks * 16 + (lane & 15)) * 272
                             + warp_n * 64 + ntp * 32 + (lane >> 4) * 16;
                uint32_t bb[4];
                ldsm4t(bb, ro);
                #pragma unroll
                for (int mt = 0; mt < 4; mt++) {
                    mma16816(acc[mt][2*ntp],     ah[mt], bb);
                    mma16816(acc[mt][2*ntp + 1], ah[mt], bb + 2);
                }
            }
        }
        __syncthreads();
    }

    const int g = lane >> 2, tg = lane & 3;
    #pragma unroll
    for (int mt = 0; mt < 4; mt++) {
        #pragma unroll
        for (int nt = 0; nt < 4; nt++) {
            const int c  = n0 + warp_n * 32 + nt * 8 + tg * 2;
            const int r0 = m0 + warp_m * 64 + mt * 16 + g;
            #pragma unroll
            for (int h = 0; h < 2; h++) {
                const int r = r0 + h * 8;
                float2 v = make_float2(acc[mt][nt][2*h], acc[mt][nt][2*h+1]);
                if (EPI == 0) {
                    const int bb2 = r >> 11, t = r & 2047;
                    const int mat = c >> 10, cc = c & 1023;
                    const int head = cc >> 6, d = cc & 63;
                    size_t o = (((size_t)(bb2 * HEADS + head) * TT + t) * HS + d) >> 1;
                    if (mat == 0) {
                        ((__half2*)g_qhi)[o] = __floats2half2_rn(v.x * QSCALE, v.y * QSCALE);
                    } else if (mat == 1) {
                        ((__half2*)g_khi)[o] = __floats2half2_rn(v.x, v.y);
                    } else {
                        ((__half2*)g_vhi)[o] = __floats2half2_rn(v.x, v.y);
                    }
                } else {
                    float2 bv = *(const float2*)(bias + c);
                    v.x += bv.x; v.y += bv.y;
                    *(float2*)(Cout + (size_t)r * EMB + c) = v;
                }
            }
        }
    }
}

// ---------------------------------------------------------------------------
// Tensor-core flash attention (R11-validated, byte-frozen).
// fp16, exp2-domain softmax, LPT grid, de-phased warps.
// ---------------------------------------------------------------------------
#define ATILE_B  (64 * 144)            // 9216 B per 64-row tile
#define ASTAGE_B (2 * ATILE_B)         // Khi, Vhi = 18432
#define ATT_SMEM (4 * ASTAGE_B)        // 73728 (4 buffers; covers Q staging)

__global__ __launch_bounds__(256, 2)
void attn_mma()
{
    extern __shared__ char sm[];
    const uint32_t sb = smem_u32(sm);
    const int tid = threadIdx.x, wid = tid >> 5, lane = tid & 31;
    const int bh = blockIdx.x;                     // 0..31
    const int qt = gridDim.y - 1 - blockIdx.y;     // heavy tiles first, globally
    const int q0 = qt * 128;
    const int g = lane >> 2, tg = lane & 3;

    // ---- stage Q into smem, then ldmatrix to registers ----
    {
        const __half* Qh = g_qhi + ((size_t)bh * TT + q0) * HS;
        #pragma unroll
        for (int i = 0; i < 4; i++) {
            int idx = i * 256 + tid;               // 0..1023
            int r = idx >> 3, c8 = idx & 7;
            *(uint4*)(sm + r * 144 + c8 * 16) = *(const uint4*)(Qh + r * HS + c8 * 8);
        }
    }
    __syncthreads();
    uint32_t qh[4][4];
    #pragma unroll
    for (int kg = 0; kg < 4; kg++) {
        uint32_t a = sb + (uint32_t)(wid * 16 + (lane & 15)) * 144 + kg * 32 + (lane >> 4) * 16;
        ldsm4(qh[kg], a);
    }
    __syncthreads();

    // ---- K/V pipeline: buffer = tile & 3 ----
    auto issueKV = [&](int kt) {
        const uint32_t dstb = sb + (kt & 3) * ASTAGE_B;
        const size_t rowb = ((size_t)bh * TT + kt * 64) * HS;
        #pragma unroll
        for (int i = 0; i < 4; i++) {
            int idx = i * 256 + tid;               // 0..1023
            int mtx = idx >> 9;                    // 0 Khi 1 Vhi
            int r = (idx >> 3) & 63, c8 = idx & 7;
            const __half* p = (mtx == 0 ? g_khi : g_vhi) + rowb + r * HS + c8 * 8;
            cp16(dstb + mtx * ATILE_B + r * 144 + c8 * 16, p);
        }
        cp_commit();
    };

    float oacc[8][4];
    #pragma unroll
    for (int nt = 0; nt < 8; nt++)
        #pragma unroll
        for (int c = 0; c < 4; c++) oacc[nt][c] = 0.f;
    float mrow[2] = {-1e30f, -1e30f}, lrow[2] = {0.f, 0.f};

    const int dq = (q0 + wid * 16) >> 6;           // warp's diagonal 64-tile
    const int NT = 2 * qt + 2;                     // always even
    const int first = wid & 1;                     // de-phase: odd warps reverse

    issueKV(0); issueKV(1);
    if (NT > 2) { issueKV(2); issueKV(3); }

    for (int j = 0; j < NT / 2; j++) {
        if (2 * j + 3 >= NT) cp_wait<0>(); else cp_wait<2>();
        __syncthreads();

        #pragma unroll
        for (int u = 0; u < 2; u++) {
            const int tt = first ^ u;
            const int kt = 2 * j + tt;
            if (kt > dq) continue;
            const uint32_t base = sb + (kt & 3) * ASTAGE_B;

            // S = Q K^T  (paired ldsm4 for K)   [exp2 domain]
            float sacc[8][4];
            #pragma unroll
            for (int nt = 0; nt < 8; nt++)
                #pragma unroll
                for (int c = 0; c < 4; c++) sacc[nt][c] = 0.f;

            #pragma unroll
            for (int kg = 0; kg < 4; kg++) {
                const uint32_t kbb = kg * 32 + ((lane >> 3) & 1) * 16;
                #pragma unroll
                for (int ntp = 0; ntp < 4; ntp++) {
                    uint32_t ro = base + (uint32_t)(ntp * 16
                                 + (lane >> 4) * 8 + (lane & 7)) * 144 + kbb;
                    uint32_t kb4[4];
                    ldsm4(kb4, ro);
                    mma16816(sacc[2*ntp],     qh[kg], kb4);
                    mma16816(sacc[2*ntp + 1], qh[kg], kb4 + 2);
                }
            }

            // causal mask on the diagonal tile
            if (kt == dq) {
                const int rl = ((q0 + wid * 16) & 63) + g;
                #pragma unroll
                for (int nt = 0; nt < 8; nt++) {
                    int c0 = nt * 8 + tg * 2;
                    if (c0     > rl)     sacc[nt][0] = -1e30f;
                    if (c0 + 1 > rl)     sacc[nt][1] = -1e30f;
                    if (c0     > rl + 8) sacc[nt][2] = -1e30f;
                    if (c0 + 1 > rl + 8) sacc[nt][3] = -1e30f;
                }
            }

            // online softmax in exp2 domain (rows g, g+8; quad reduction)
            #pragma unroll
            for (int r = 0; r < 2; r++) {
                float mx = -1e30f;
                #pragma unroll
                for (int nt = 0; nt < 8; nt++)
                    mx = fmaxf(mx, fmaxf(sacc[nt][2*r], sacc[nt][2*r+1]));
                mx = fmaxf(mx, __shfl_xor_sync(0xffffffffu, mx, 1));
                mx = fmaxf(mx, __shfl_xor_sync(0xffffffffu, mx, 2));
                float mnew = fmaxf(mrow[r], mx);
                float corr = exp2f(mrow[r] - mnew);
                float rs = 0.f;
                #pragma unroll
                for (int nt = 0; nt < 8; nt++) {
                    float p0 = exp2f(sacc[nt][2*r]   - mnew);
                    float p1 = exp2f(sacc[nt][2*r+1] - mnew);
                    sacc[nt][2*r] = p0; sacc[nt][2*r+1] = p1;
                    rs += p0 + p1;
                }
                rs += __shfl_xor_sync(0xffffffffu, rs, 1);
                rs += __shfl_xor_sync(0xffffffffu, rs, 2);
                lrow[r] = lrow[r] * corr + rs;
                mrow[r] = mnew;
                #pragma unroll
                for (int nt = 0; nt < 8; nt++) {
                    oacc[nt][2*r] *= corr; oacc[nt][2*r+1] *= corr;
                }
            }

            // O += P V  (paired ldsm4t for V)
            #pragma unroll
            for (int kg = 0; kg < 4; kg++) {
                uint32_t ph[4];
                #pragma unroll
                for (int q = 0; q < 4; q++) {
                    ph[q] = packh2(sacc[2*kg + (q >> 1)][(q & 1) * 2],
                                   sacc[2*kg + (q >> 1)][(q & 1) * 2 + 1]);
                }
                #pragma unroll
                for (int ntp = 0; ntp < 4; ntp++) {
                    uint32_t ro = base + ATILE_B
                                 + (uint32_t)(kg * 16 + (lane & 15)) * 144
                                 + ntp * 32 + (lane >> 4) * 16;
                    uint32_t vb4[4];
                    ldsm4t(vb4, ro);
                    mma16816(oacc[2*ntp],     ph, vb4);
                    mma16816(oacc[2*ntp + 1], ph, vb4 + 2);
                }
            }
        }
        __syncthreads();
        if (2 * j + 4 < NT) issueKV(2 * j + 4);
        if (2 * j + 5 < NT) issueKV(2 * j + 5);
    }

    // epilogue: write fp16 directly as the proj-GEMM A operand
    const int b = bh >> 4, h = bh & 15;
    #pragma unroll
    for (int r = 0; r < 2; r++) {
        float inv = 1.0f / lrow[r];
        int t = q0 + wid * 16 + g + r * 8;
        size_t rowo = ((size_t)(b * TT + t)) * EMB + h * HS;
        #pragma unroll
        for (int nt = 0; nt < 8; nt++) {
            size_t o = (rowo + nt * 8 + tg * 2) >> 1;
            ((__half2*)g_ahi)[o] =
                __floats2half2_rn(oacc[nt][2*r] * inv, oacc[nt][2*r+1] * inv);
        }
    }
}

// ---------------------------------------------------------------------------
extern "C" void kernel_launch(void* const* d_in, const int* in_sizes, int n_in,
                              void* d_out, int out_size)
{
    const float* x      = (const float*)d_in[0];
    const float* w_qkv  = (const float*)d_in[1];
    const float* w_proj = (const float*)d_in[2];
    const float* b_proj = (const float*)d_in[3];
    float* out = (float*)d_out;

    cudaFuncSetAttribute(attn_mma, cudaFuncAttributeMaxDynamicSharedMemorySize, ATT_SMEM);
    cudaFuncSetAttribute(mma_gemm<0>, cudaFuncAttributeMaxDynamicSharedMemorySize, GEMM_SMEM);
    cudaFuncSetAttribute(mma_gemm<1>, cudaFuncAttributeMaxDynamicSharedMemorySize, GEMM_SMEM);

    __half *xhi, *ahi, *wqhi, *wphi;
    cudaGetSymbolAddress((void**)&xhi,  g_xhi);
    cudaGetSymbolAddress((void**)&ahi,  g_ahi);
    cudaGetSymbolAddress((void**)&wqhi, g_wqhi);
    cudaGetSymbolAddress((void**)&wphi, g_wphi);

    // 1. prep: pure elementwise fp32->fp16 (x + both weights, one launch)
    prep_all<<<8192, 256>>>((const float4*)x,      (__half2*)xhi,
                            (const float4*)w_qkv,  (__half2*)wqhi,
                            (const float4*)w_proj, (__half2*)wphi);

    // 2. QKV GEMM (fp16, BK=64, W native [K][N]) -> q (xQSCALE), k, v
    mma_gemm<0><<<dim3(3 * EMB / 128, NROWS / 128), 256, GEMM_SMEM>>>(
        xhi, wqhi, nullptr, nullptr, 3 * EMB);

    // 3. tensor-core causal flash attention (LPT grid, de-phased warps)
    attn_mma<<<dim3(BB * HEADS, TT / 128), 256, ATT_SMEM>>>();

    // 4. output projection (fp16, BK=64, W native [K][N]) + bias
    mma_gemm<1><<<dim3(EMB / 128, NROWS / 128), 256, GEMM_SMEM>>>(
        ahi, wphi, b_proj, out, EMB);
}

// round 14
// speedup vs baseline: 3.1952x; 1.0147x over previous
#include <cuda_runtime.h>
#include <cuda_fp16.h>
#include <cstdint>
#include <math.h>

// Problem constants
#define BB 2
#define TT 2048
#define EMB 1024
#define HEADS 16
#define HS 64
#define NROWS (BB*TT)          // 4096
#define GK 1024                // K for both GEMMs

// Q pre-scale: hs^-0.5 * log2(e)  (softmax runs in exp2 domain)
#define QSCALE 0.180336880f

// ---------------------------------------------------------------------------
// Scratch (__device__ globals; allocation-free rule). 1-term fp16 everywhere.
// Weights stay in native [K][N] layout (no transpose) — B frags via ldsm4t.
// ---------------------------------------------------------------------------
__device__ __half g_qhi[(size_t)BB*HEADS*TT*HS];   // [bh][t][d], pre-scaled QSCALE
__device__ __half g_khi[(size_t)BB*HEADS*TT*HS];
__device__ __half g_vhi[(size_t)BB*HEADS*TT*HS];

__device__ __half g_xhi[(size_t)NROWS*GK];
__device__ __half g_ahi[(size_t)NROWS*GK];         // attention out (proj input)
__device__ __half g_wqhi[(size_t)GK*3*EMB];        // [1024][3072] K-major rows
__device__ __half g_wphi[(size_t)GK*EMB];          // [1024][1024] K-major rows

// ---------------------------------------------------------------------------
// PTX helpers (portable sm_80+ subset: ldmatrix / mma.sync / cp.async)
// ---------------------------------------------------------------------------
__device__ __forceinline__ uint32_t smem_u32(const void* p) {
    uint32_t a;
    asm("{ .reg .u64 t; cvta.to.shared.u64 t, %1; cvt.u32.u64 %0, t; }" : "=r"(a) : "l"(p));
    return a;
}
__device__ __forceinline__ void cp16(uint32_t dst, const void* src) {
    asm volatile("cp.async.cg.shared.global [%0], [%1], 16;" :: "r"(dst), "l"(src));
}
__device__ __forceinline__ void cp_commit() {
    asm volatile("cp.async.commit_group;" ::: "memory");
}
template<int N>
__device__ __forceinline__ void cp_wait() {
    asm volatile("cp.async.wait_group %0;" :: "n"(N) : "memory");
}
__device__ __forceinline__ void ldsm4(uint32_t* r, uint32_t a) {
    asm volatile("ldmatrix.sync.aligned.m8n8.x4.shared.b16 {%0,%1,%2,%3}, [%4];"
        : "=r"(r[0]), "=r"(r[1]), "=r"(r[2]), "=r"(r[3]) : "r"(a));
}
// trans x4: [k][n]-stored rows -> col-major B fragments (validated on V path)
__device__ __forceinline__ void ldsm4t(uint32_t* r, uint32_t a) {
    asm volatile("ldmatrix.sync.aligned.m8n8.x4.trans.shared.b16 {%0,%1,%2,%3}, [%4];"
        : "=r"(r[0]), "=r"(r[1]), "=r"(r[2]), "=r"(r[3]) : "r"(a));
}
__device__ __forceinline__ void mma16816(float* d, const uint32_t* a, const uint32_t* b) {
    asm volatile("mma.sync.aligned.m16n8k16.row.col.f32.f16.f16.f32 "
        "{%0,%1,%2,%3}, {%4,%5,%6,%7}, {%8,%9}, {%0,%1,%2,%3};"
        : "+f"(d[0]), "+f"(d[1]), "+f"(d[2]), "+f"(d[3])
        : "r"(a[0]), "r"(a[1]), "r"(a[2]), "r"(a[3]), "r"(b[0]), "r"(b[1]));
}
__device__ __forceinline__ uint32_t packh2(float a, float b) {
    __half2 h = __floats2half2_rn(a, b);
    return *(uint32_t*)&h;
}
// guaranteed single-MUFU exp2 (independent of fast-math flags)
__device__ __forceinline__ float ex2(float x) {
    float y;
    asm("ex2.approx.ftz.f32 %0, %1;" : "=f"(y) : "f"(x));
    return y;
}

// ---------------------------------------------------------------------------
// Prep: pure elementwise fp32 -> fp16 convert of x, w_qkv, w_proj (flat).
// ---------------------------------------------------------------------------
#define NX4  1048576
#define NWQ4 786432

__global__ void prep_all(const float4* __restrict__ x, __half2* __restrict__ xo,
                         const float4* __restrict__ wq, __half2* __restrict__ wqo,
                         const float4* __restrict__ wp, __half2* __restrict__ wpo)
{
    int i = blockIdx.x * 256 + threadIdx.x;
    const float4* src; __half2* dst;
    if (i < NX4)             { src = x;  dst = xo; }
    else if (i < NX4 + NWQ4) { src = wq; dst = wqo; i -= NX4; }
    else                     { src = wp; dst = wpo; i -= NX4 + NWQ4; }
    float4 v = src[i];
    dst[2*i]   = __floats2half2_rn(v.x, v.y);
    dst[2*i+1] = __floats2half2_rn(v.z, v.w);
}

// ---------------------------------------------------------------------------
// HMMA GEMM (R12-validated): C[M,N] = A[M,1024] * W[1024,N], fp16.
// A [M][K] K-major (144B rows, ldsm4); W [K][N] native (272B rows, ldsm4t).
// 128x128 tile, BK=64 (16 iters), 8 warps (2x4), double buffer, 2 CTA/SM.
// PDL: grid-dependency sync before any global reads.
// ---------------------------------------------------------------------------
#define BKG 64
#define MATA (128 * 144)              // 18432 B A tile
#define MATW (64 * 272)               // 17408 B W tile
#define STAGEB (MATA + MATW)          // 35840
#define GEMM_SMEM (2 * STAGEB)        // 71680

template<int EPI>
__global__ __launch_bounds__(256, 2)
void mma_gemm(const __half* __restrict__ Ahi, const __half* __restrict__ Wm,
              const float* __restrict__ bias, float* __restrict__ Cout, int Nw)
{
    cudaGridDependencySynchronize();

    extern __shared__ char smc[];
    const uint32_t sb = smem_u32(smc);

    const int tid = threadIdx.x;
    const int wid = tid >> 5, lane = tid & 31;
    const int warp_m = wid >> 2;      // 0..1
    const int warp_n = wid & 3;       // 0..3
    const int m0 = blockIdx.y * 128, n0 = blockIdx.x * 128;

    auto issue = [&](int kc, int s) {
        const uint32_t dstb = sb + s * STAGEB;
        #pragma unroll
        for (int i = 0; i < 8; i++) {
            int idx = i * 256 + tid;            // 0..2047
            if (idx < 1024) {                   // A tile: 128 rows x 8 chunks
                int r = idx >> 3, c8 = idx & 7;
                cp16(dstb + r * 144 + c8 * 16,
                     Ahi + (size_t)(m0 + r) * GK + kc * BKG + c8 * 8);
            } else {                            // W tile: 64 k-rows x 16 chunks
                int i2 = idx - 1024;
                int r = i2 >> 4, c16 = i2 & 15;
                cp16(dstb + MATA + r * 272 + c16 * 16,
                     Wm + (size_t)(kc * BKG + r) * Nw + n0 + c16 * 8);
            }
        }
        cp_commit();
    };

    float acc[4][4][4];
    #pragma unroll
    for (int a = 0; a < 4; a++)
        #pragma unroll
        for (int b = 0; b < 4; b++)
            #pragma unroll
            for (int c = 0; c < 4; c++) acc[a][b][c] = 0.f;

    issue(0, 0);
    const int NIT = GK / BKG;           // 16
    for (int kc = 0; kc < NIT; kc++) {
        const int s = kc & 1;
        if (kc + 1 < NIT) { issue(kc + 1, s ^ 1); cp_wait<1>(); }
        else              { cp_wait<0>(); }
        __syncthreads();

        const uint32_t Ah = sb + s * STAGEB;
        const uint32_t Wh = Ah + MATA;

        #pragma unroll
        for (int ks = 0; ks < 4; ks++) {
            const uint32_t kb = ks * 32 + (lane >> 4) * 16;
            uint32_t ah[4][4];
            #pragma unroll
            for (int mt = 0; mt < 4; mt++) {
                uint32_t ro = Ah + (uint32_t)(warp_m * 64 + mt * 16 + (lane & 15)) * 144 + kb;
                ldsm4(ah[mt], ro);
            }
            #pragma unroll
            for (int ntp = 0; ntp < 2; ntp++) {
                uint32_t ro = Wh + (uint32_t)(ks * 16 + (lane & 15)) * 272
                             + warp_n * 64 + ntp * 32 + (lane >> 4) * 16;
                uint32_t bb[4];
                ldsm4t(bb, ro);
                #pragma unroll
                for (int mt = 0; mt < 4; mt++) {
                    mma16816(acc[mt][2*ntp],     ah[mt], bb);
                    mma16816(acc[mt][2*ntp + 1], ah[mt], bb + 2);
                }
            }
        }
        __syncthreads();
    }

    const int g = lane >> 2, tg = lane & 3;
    #pragma unroll
    for (int mt = 0; mt < 4; mt++) {
        #pragma unroll
        for (int nt = 0; nt < 4; nt++) {
            const int c  = n0 + warp_n * 32 + nt * 8 + tg * 2;
            const int r0 = m0 + warp_m * 64 + mt * 16 + g;
            #pragma unroll
            for (int h = 0; h < 2; h++) {
                const int r = r0 + h * 8;
                float2 v = make_float2(acc[mt][nt][2*h], acc[mt][nt][2*h+1]);
                if (EPI == 0) {
                    const int bb2 = r >> 11, t = r & 2047;
                    const int mat = c >> 10, cc = c & 1023;
                    const int head = cc >> 6, d = cc & 63;
                    size_t o = (((size_t)(bb2 * HEADS + head) * TT + t) * HS + d) >> 1;
                    if (mat == 0) {
                        ((__half2*)g_qhi)[o] = __floats2half2_rn(v.x * QSCALE, v.y * QSCALE);
                    } else if (mat == 1) {
                        ((__half2*)g_khi)[o] = __floats2half2_rn(v.x, v.y);
                    } else {
                        ((__half2*)g_vhi)[o] = __floats2half2_rn(v.x, v.y);
                    }
                } else {
                    float2 bv = *(const float2*)(bias + c);
                    v.x += bv.x; v.y += bv.y;
                    *(float2*)(Cout + (size_t)r * EMB + c) = v;
                }
            }
        }
    }
}

// ---------------------------------------------------------------------------
// Tensor-core flash attention (R11-validated structure).
// fp16, exp2-domain softmax (ex2.approx), LPT grid, de-phased warps, PDL.
// ---------------------------------------------------------------------------
#define ATILE_B  (64 * 144)            // 9216 B per 64-row tile
#define ASTAGE_B (2 * ATILE_B)         // Khi, Vhi = 18432
#define ATT_SMEM (4 * ASTAGE_B)        // 73728 (4 buffers; covers Q staging)

__global__ __launch_bounds__(256, 2)
void attn_mma()
{
    cudaGridDependencySynchronize();

    extern __shared__ char sm[];
    const uint32_t sb = smem_u32(sm);
    const int tid = threadIdx.x, wid = tid >> 5, lane = tid & 31;
    const int bh = blockIdx.x;                     // 0..31
    const int qt = gridDim.y - 1 - blockIdx.y;     // heavy tiles first, globally
    const int q0 = qt * 128;
    const int g = lane >> 2, tg = lane & 3;

    // ---- stage Q into smem, then ldmatrix to registers ----
    {
        const __half* Qh = g_qhi + ((size_t)bh * TT + q0) * HS;
        #pragma unroll
        for (int i = 0; i < 4; i++) {
            int idx = i * 256 + tid;               // 0..1023
            int r = idx >> 3, c8 = idx & 7;
            *(uint4*)(sm + r * 144 + c8 * 16) = *(const uint4*)(Qh + r * HS + c8 * 8);
        }
    }
    __syncthreads();
    uint32_t qh[4][4];
    #pragma unroll
    for (int kg = 0; kg < 4; kg++) {
        uint32_t a = sb + (uint32_t)(wid * 16 + (lane & 15)) * 144 + kg * 32 + (lane >> 4) * 16;
        ldsm4(qh[kg], a);
    }
    __syncthreads();

    // ---- K/V pipeline: buffer = tile & 3 ----
    auto issueKV = [&](int kt) {
        const uint32_t dstb = sb + (kt & 3) * ASTAGE_B;
        const size_t rowb = ((size_t)bh * TT + kt * 64) * HS;
        #pragma unroll
        for (int i = 0; i < 4; i++) {
            int idx = i * 256 + tid;               // 0..1023
            int mtx = idx >> 9;                    // 0 Khi 1 Vhi
            int r = (idx >> 3) & 63, c8 = idx & 7;
            const __half* p = (mtx == 0 ? g_khi : g_vhi) + rowb + r * HS + c8 * 8;
            cp16(dstb + mtx * ATILE_B + r * 144 + c8 * 16, p);
        }
        cp_commit();
    };

    float oacc[8][4];
    #pragma unroll
    for (int nt = 0; nt < 8; nt++)
        #pragma unroll
        for (int c = 0; c < 4; c++) oacc[nt][c] = 0.f;
    float mrow[2] = {-1e30f, -1e30f}, lrow[2] = {0.f, 0.f};

    const int dq = (q0 + wid * 16) >> 6;           // warp's diagonal 64-tile
    const int NT = 2 * qt + 2;                     // always even
    const int first = wid & 1;                     // de-phase: odd warps reverse

    issueKV(0); issueKV(1);
    if (NT > 2) { issueKV(2); issueKV(3); }

    for (int j = 0; j < NT / 2; j++) {
        if (2 * j + 3 >= NT) cp_wait<0>(); else cp_wait<2>();
        __syncthreads();

        #pragma unroll
        for (int u = 0; u < 2; u++) {
            const int tt = first ^ u;
            const int kt = 2 * j + tt;
            if (kt > dq) continue;
            const uint32_t base = sb + (kt & 3) * ASTAGE_B;

            // S = Q K^T  (paired ldsm4 for K)   [exp2 domain]
            float sacc[8][4];
            #pragma unroll
            for (int nt = 0; nt < 8; nt++)
                #pragma unroll
                for (int c = 0; c < 4; c++) sacc[nt][c] = 0.f;

            #pragma unroll
            for (int kg = 0; kg < 4; kg++) {
                const uint32_t kbb = kg * 32 + ((lane >> 3) & 1) * 16;
                #pragma unroll
                for (int ntp = 0; ntp < 4; ntp++) {
                    uint32_t ro = base + (uint32_t)(ntp * 16
                                 + (lane >> 4) * 8 + (lane & 7)) * 144 + kbb;
                    uint32_t kb4[4];
                    ldsm4(kb4, ro);
                    mma16816(sacc[2*ntp],     qh[kg], kb4);
                    mma16816(sacc[2*ntp + 1], qh[kg], kb4 + 2);
                }
            }

            // causal mask on the diagonal tile
            if (kt == dq) {
                const int rl = ((q0 + wid * 16) & 63) + g;
                #pragma unroll
                for (int nt = 0; nt < 8; nt++) {
                    int c0 = nt * 8 + tg * 2;
                    if (c0     > rl)     sacc[nt][0] = -1e30f;
                    if (c0 + 1 > rl)     sacc[nt][1] = -1e30f;
                    if (c0     > rl + 8) sacc[nt][2] = -1e30f;
                    if (c0 + 1 > rl + 8) sacc[nt][3] = -1e30f;
                }
            }

            // online softmax in exp2 domain (rows g, g+8; quad reduction)
            #pragma unroll
            for (int r = 0; r < 2; r++) {
                float mx = -1e30f;
                #pragma unroll
                for (int nt = 0; nt < 8; nt++)
                    mx = fmaxf(mx, fmaxf(sacc[nt][2*r], sacc[nt][2*r+1]));
                mx = fmaxf(mx, __shfl_xor_sync(0xffffffffu, mx, 1));
                mx = fmaxf(mx, __shfl_xor_sync(0xffffffffu, mx, 2));
                float mnew = fmaxf(mrow[r], mx);
                float corr = ex2(mrow[r] - mnew);
                float rs = 0.f;
                #pragma unroll
                for (int nt = 0; nt < 8; nt++) {
                    float p0 = ex2(sacc[nt][2*r]   - mnew);
                    float p1 = ex2(sacc[nt][2*r+1] - mnew);
                    sacc[nt][2*r] = p0; sacc[nt][2*r+1] = p1;
                    rs += p0 + p1;
                }
                rs += __shfl_xor_sync(0xffffffffu, rs, 1);
                rs += __shfl_xor_sync(0xffffffffu, rs, 2);
                lrow[r] = lrow[r] * corr + rs;
                mrow[r] = mnew;
                #pragma unroll
                for (int nt = 0; nt < 8; nt++) {
                    oacc[nt][2*r] *= corr; oacc[nt][2*r+1] *= corr;
                }
            }

            // O += P V  (paired ldsm4t for V)
            #pragma unroll
            for (int kg = 0; kg < 4; kg++) {
                uint32_t ph[4];
                #pragma unroll
                for (int q = 0; q < 4; q++) {
                    ph[q] = packh2(sacc[2*kg + (q >> 1)][(q & 1) * 2],
                                   sacc[2*kg + (q >> 1)][(q & 1) * 2 + 1]);
                }
                #pragma unroll
                for (int ntp = 0; ntp < 4; ntp++) {
                    uint32_t ro = base + ATILE_B
                                 + (uint32_t)(kg * 16 + (lane & 15)) * 144
                                 + ntp * 32 + (lane >> 4) * 16;
                    uint32_t vb4[4];
                    ldsm4t(vb4, ro);
                    mma16816(oacc[2*ntp],     ph, vb4);
                    mma16816(oacc[2*ntp + 1], ph, vb4 + 2);
                }
            }
        }
        __syncthreads();
        if (2 * j + 4 < NT) issueKV(2 * j + 4);
        if (2 * j + 5 < NT) issueKV(2 * j + 5);
    }

    // epilogue: write fp16 directly as the proj-GEMM A operand
    const int b = bh >> 4, h = bh & 15;
    #pragma unroll
    for (int r = 0; r < 2; r++) {
        float inv = 1.0f / lrow[r];
        int t = q0 + wid * 16 + g + r * 8;
        size_t rowo = ((size_t)(b * TT + t)) * EMB + h * HS;
        #pragma unroll
        for (int nt = 0; nt < 8; nt++) {
            size_t o = (rowo + nt * 8 + tg * 2) >> 1;
            ((__half2*)g_ahi)[o] =
                __floats2half2_rn(oacc[nt][2*r] * inv, oacc[nt][2*r+1] * inv);
        }
    }
}

// ---------------------------------------------------------------------------
// Host: launch with programmatic stream serialization (PDL) on the three
// dependent kernels; prep launches normally.
// ---------------------------------------------------------------------------
template<typename K, typename... Args>
static void launch_pdl(K kern, dim3 grid, dim3 block, size_t smem, Args... args)
{
    cudaLaunchConfig_t cfg = {};
    cfg.gridDim = grid;
    cfg.blockDim = block;
    cfg.dynamicSmemBytes = smem;
    cfg.stream = 0;
    cudaLaunchAttribute attrs[1];
    attrs[0].id = cudaLaunchAttributeProgrammaticStreamSerialization;
    attrs[0].val.programmaticStreamSerializationAllowed = 1;
    cfg.attrs = attrs;
    cfg.numAttrs = 1;
    cudaLaunchKernelEx(&cfg, kern, args...);
}

extern "C" void kernel_launch(void* const* d_in, const int* in_sizes, int n_in,
                              void* d_out, int out_size)
{
    const float* x      = (const float*)d_in[0];
    const float* w_qkv  = (const float*)d_in[1];
    const float* w_proj = (const float*)d_in[2];
    const float* b_proj = (const float*)d_in[3];
    float* out = (float*)d_out;

    cudaFuncSetAttribute(attn_mma, cudaFuncAttributeMaxDynamicSharedMemorySize, ATT_SMEM);
    cudaFuncSetAttribute(mma_gemm<0>, cudaFuncAttributeMaxDynamicSharedMemorySize, GEMM_SMEM);
    cudaFuncSetAttribute(mma_gemm<1>, cudaFuncAttributeMaxDynamicSharedMemorySize, GEMM_SMEM);

    __half *xhi, *ahi, *wqhi, *wphi;
    cudaGetSymbolAddress((void**)&xhi,  g_xhi);
    cudaGetSymbolAddress((void**)&ahi,  g_ahi);
    cudaGetSymbolAddress((void**)&wqhi, g_wqhi);
    cudaGetSymbolAddress((void**)&wphi, g_wphi);

    // 1. prep: pure elementwise fp32->fp16 (x + both weights, one launch)
    prep_all<<<8192, 256>>>((const float4*)x,      (__half2*)xhi,
                            (const float4*)w_qkv,  (__half2*)wqhi,
                            (const float4*)w_proj, (__half2*)wphi);

    // 2. QKV GEMM (fp16, BK=64, W native [K][N]) -> q (xQSCALE), k, v
    launch_pdl(mma_gemm<0>, dim3(3 * EMB / 128, NROWS / 128), dim3(256), GEMM_SMEM,
               (const __half*)xhi, (const __half*)wqhi,
               (const float*)nullptr, (float*)nullptr, 3 * EMB);

    // 3. tensor-core causal flash attention (LPT grid, de-phased warps)
    launch_pdl(attn_mma, dim3(BB * HEADS, TT / 128), dim3(256), ATT_SMEM);

    // 4. output projection (fp16, BK=64, W native [K][N]) + bias
    launch_pdl(mma_gemm<1>, dim3(EMB / 128, NROWS / 128), dim3(256), GEMM_SMEM,
               (const __half*)ahi, (const __half*)wphi,
               b_proj, out, EMB);
}